// round 13
// baseline (speedup 1.0000x reference)
#include <cuda_runtime.h>
#include <cuda_fp16.h>
#include <cstdint>

#define B_      2048
#define ADIM    14
#define C_      128
#define H_      256
#define E_      182
#define NNODES  (B_*ADIM)   /* 28672 */
#define NROWS   (B_*E_)     /* 372736 */
#define NPAIR   (B_/2)      /* 1024 */

// ---------------- device scratch (no allocs allowed) ----------------
__device__ __align__(16) __half g_W2h [H_*H_];        // lin2_w fp16, row-major (g, h)
__device__ __align__(16) __half g_Wcat[512*C_];       // [W_left rows | W_right rows], k-contig
__device__ __align__(16) __half g_Xh  [NNODES*C_];    // x = g + state, fp16
__device__ __align__(16) __half g_Yh  [(size_t)NNODES*512]; // [yl(256,+b1) | yr(256)] fp16

// ---------------- mma / barrier helpers ----------------
__device__ __forceinline__ void ldsm_x4(unsigned &r0,unsigned &r1,unsigned &r2,unsigned &r3, unsigned a){
  asm volatile("ldmatrix.sync.aligned.m8n8.x4.shared.b16 {%0,%1,%2,%3},[%4];"
    :"=r"(r0),"=r"(r1),"=r"(r2),"=r"(r3):"r"(a));
}
__device__ __forceinline__ void ldsm_x2(unsigned &r0,unsigned &r1, unsigned a){
  asm volatile("ldmatrix.sync.aligned.m8n8.x2.shared.b16 {%0,%1},[%2];"
    :"=r"(r0),"=r"(r1):"r"(a));
}
__device__ __forceinline__ void mma16816(float c[4], const unsigned a[4], const unsigned b[2]){
  asm volatile("mma.sync.aligned.m16n8k16.row.col.f32.f16.f16.f32 "
    "{%0,%1,%2,%3},{%4,%5,%6,%7},{%8,%9},{%0,%1,%2,%3};"
    :"+f"(c[0]),"+f"(c[1]),"+f"(c[2]),"+f"(c[3])
    :"r"(a[0]),"r"(a[1]),"r"(a[2]),"r"(a[3]),"r"(b[0]),"r"(b[1]));
}
__device__ __forceinline__ void mma16816s(float c[4], const unsigned a[4], unsigned b0, unsigned b1){
  asm volatile("mma.sync.aligned.m16n8k16.row.col.f32.f16.f16.f32 "
    "{%0,%1,%2,%3},{%4,%5,%6,%7},{%8,%9},{%0,%1,%2,%3};"
    :"+f"(c[0]),"+f"(c[1]),"+f"(c[2]),"+f"(c[3])
    :"r"(a[0]),"r"(a[1]),"r"(a[2]),"r"(a[3]),"r"(b0),"r"(b1));
}
__device__ __forceinline__ void cp16(unsigned dst, const void* src){
  asm volatile("cp.async.cg.shared.global [%0], [%1], 16;" :: "r"(dst), "l"(src));
}
#define CP_COMMIT() asm volatile("cp.async.commit_group;" ::: "memory")
#define CP_WAIT0()  asm volatile("cp.async.wait_group 0;" ::: "memory")
#define BAR_SYNC(id, n)   asm volatile("bar.sync %0, %1;"   :: "r"(id), "r"(n) : "memory")
#define BAR_ARRIVE(id, n) asm volatile("bar.arrive %0, %1;" :: "r"(id), "r"(n) : "memory")

__device__ __forceinline__ float lky(float v){ return v > 0.f ? v : 0.01f*v; }
__device__ __forceinline__ float softplus_(float x){ return fmaxf(x,0.f) + log1pf(expf(-fabsf(x))); }

// ---------------- K0: weight conversion ----------------
__global__ void k_prep(const float* __restrict__ lin1_w, const float* __restrict__ lin2_w){
  int i = blockIdx.x*blockDim.x + threadIdx.x;   // 65536 threads
  if (i < H_*H_) g_W2h[i] = __float2half(lin2_w[i]);
  if (i < 512*C_){
    int o = i >> 7, c = i & 127;
    float v = (o < H_) ? lin1_w[o*(2*C_) + c] : lin1_w[(o-H_)*(2*C_) + C_ + c];
    g_Wcat[i] = __float2half(v);
  }
}

// ---------------- K1: s_bar -> g -> X (8 batches per block) ----------------
__global__ __launch_bounds__(256,1)
void k1_build(const float* __restrict__ state, const float* __restrict__ conv_w,
              const float* __restrict__ conv_b){
  extern __shared__ float sm1[];
  float* cw   = sm1;                 // 128 x 129
  float* sbar = cw + 128*129;        // 8 x 128
  float* gg   = sbar + 8*128;        // 8 x 128
  int tid = threadIdx.x;
  int b0  = blockIdx.x * 8;

  for (int i = tid; i < 128*128; i += 256){ int r = i>>7, c = i&127; cw[r*129+c] = conv_w[i]; }
  for (int idx = tid; idx < 8*128; idx += 256){
    int bb = idx >> 7, c = idx & 127;
    const float* sp = state + (size_t)(b0+bb)*ADIM*C_ + c;
    float s = 0.f;
    #pragma unroll
    for (int i = 0; i < ADIM; i++) s += sp[i*C_];
    sbar[idx] = s * (1.0f/14.0f);
  }
  __syncthreads();
  #pragma unroll
  for (int u = 0; u < 4; u++){
    int o = tid + u*256;
    int bb = o >> 7, h = o & 127;
    const float* sb = sbar + bb*128;
    const float* w  = cw + h*129;
    float acc = 0.f;
    #pragma unroll 8
    for (int c = 0; c < 128; c++) acc += sb[c]*w[c];
    gg[o] = fmaxf(acc + conv_b[h], 0.f);
  }
  __syncthreads();
  for (int idx = tid; idx < 8*ADIM*C_; idx += 256){
    int bb = idx / (ADIM*C_); int rem = idx - bb*(ADIM*C_);
    int c  = rem & 127;
    size_t node = (size_t)(b0+bb)*ADIM + (rem >> 7);
    g_Xh[node*C_ + c] = __float2half(gg[bb*128 + c] + state[node*C_ + c]);
  }
}

// ---------------- K2: Y = X @ Wcat^T, fp16 out, b1 folded ----------------
__global__ __launch_bounds__(256,1)
void k2_ygemm(const float* __restrict__ lin1_b){
  extern __shared__ __half sm2[];
  __half* As = sm2;             // 128 x 136
  __half* Bs = As + 128*136;    // 128 x 136
  int tid = threadIdx.x;
  int m0 = blockIdx.x * 128, n0 = blockIdx.y * 128;

  for (int idx = tid; idx < 128*16; idx += 256){
    int r = idx >> 4, c = idx & 15;
    *(uint4*)&As[r*136 + c*8] = *(const uint4*)&g_Xh [(size_t)(m0+r)*C_ + c*8];
    *(uint4*)&Bs[r*136 + c*8] = *(const uint4*)&g_Wcat[(size_t)(n0+r)*C_ + c*8];
  }
  __syncthreads();

  int lane = tid & 31, warp = tid >> 5, wm = warp >> 2, wn = warp & 3;
  unsigned abase = (unsigned)__cvta_generic_to_shared(As);
  unsigned bbase = (unsigned)__cvta_generic_to_shared(Bs);
  float acc[4][4][4];
  #pragma unroll
  for (int i=0;i<4;i++) for (int j=0;j<4;j++) for (int q=0;q<4;q++) acc[i][j][q]=0.f;

  int rA = (lane & 7) + ((lane >> 3) & 1) * 8;
  int cA = (lane >> 4) * 8;
  int l16 = lane & 15;
  int rB = l16 & 7;
  int cB = (l16 >> 3) * 8;

  #pragma unroll
  for (int kk = 0; kk < 8; kk++){
    int k0 = kk*16;
    unsigned a[4][4], b[4][2];
    #pragma unroll
    for (int mi = 0; mi < 4; mi++){
      int row = wm*64 + mi*16 + rA;
      ldsm_x4(a[mi][0],a[mi][1],a[mi][2],a[mi][3], abase + (row*136 + k0 + cA)*2);
    }
    #pragma unroll
    for (int ni = 0; ni < 4; ni++){
      int row = wn*32 + ni*8 + rB;
      ldsm_x2(b[ni][0],b[ni][1], bbase + (row*136 + k0 + cB)*2);
    }
    #pragma unroll
    for (int mi = 0; mi < 4; mi++)
      #pragma unroll
      for (int ni = 0; ni < 4; ni++)
        mma16816(acc[mi][ni], a[mi], b[ni]);
  }
  bool leftblk = (n0 < 256);
  #pragma unroll
  for (int ni = 0; ni < 4; ni++){
    int col = n0 + wn*32 + ni*8 + ((lane & 3) << 1);
    float a0 = leftblk ? __ldg(&lin1_b[col])   : 0.f;
    float a1 = leftblk ? __ldg(&lin1_b[col+1]) : 0.f;
    #pragma unroll
    for (int mi = 0; mi < 4; mi++){
      int row = m0 + wm*64 + mi*16 + (lane >> 2);
      *(__half2*)&g_Yh[(size_t)row*512 + col] =
        __floats2half2_rn(acc[mi][ni][0] + a0, acc[mi][ni][1] + a1);
      *(__half2*)&g_Yh[(size_t)(row+8)*512 + col] =
        __floats2half2_rn(acc[mi][ni][2] + a0, acc[mi][ni][3] + a1);
    }
  }
}

// ---------------- K3: warp-specialized GEMM + builder-side heads ----------------
// 384 threads: warps 0-7 = GEMM (m64 x n32, 1m x 8n, chunk M=64, 6 chunks/pair),
// warps 8-11 = builders (H1 build, acc dots, heads, log-prob, Ys prefetch).
// Buffer lifecycle per H1[buf]: build H1 -> [ready] -> GEMM k-loop -> [id6, GEMM-only]
//   -> GEMM STS leaky(acc+b2) fp16 over H1 -> [accready] -> builder dots+heads
//   -> [id7, builder-only] -> build next H1 in same buf.
// Barriers: ready=1,2 accready=3,4 Ys-guard=5(128) gemm=6(256) builder=7(128).
__global__ __launch_bounds__(384,1)
void k3_main(const float* __restrict__ lin2_b,
             const float* __restrict__ mu_w,  const float* __restrict__ mu_b,
             const float* __restrict__ sig_w, const float* __restrict__ sig_b,
             const float* __restrict__ noise, float* __restrict__ out){
  extern __shared__ __half sm3[];
  __half* Ys  = sm3;                 // 2 x 14 x 512 = 14336 halves (one pair)
  __half* W2s = Ys + 14336;          // 256 x 264 = 67584
  __half* H1a = W2s + 67584;         // 64 x 264
  __half* H1b = H1a + 16896;         // 64 x 264
  float*  lp  = (float*)(H1b + 16896);  // 2 floats (+pad)
  // total 231424 + 16 B

  int tid  = threadIdx.x;
  int lane = tid & 31, warp = tid >> 5;          // 12 warps
  bool isg = (warp < 8);
  int warp_n = warp & 7;
  int bt = tid & 127;                             // builder-local index

  // one-time: W2 into smem (stride 264)
  for (int idx = tid; idx < 256*32; idx += 384){
    int r = idx >> 5, c = idx & 31;
    *(uint4*)&W2s[r*264 + c*8] = ((const uint4*)g_W2h)[r*32 + c];
  }
  // GEMM: per-thread b2 constants (n32 slice)
  __half2 b2c[4];
  if (isg){
    #pragma unroll
    for (int ni = 0; ni < 4; ni++){
      int col = warp_n*32 + ni*8 + ((lane & 3) << 1);
      b2c[ni] = __floats2half2_rn(__ldg(&lin2_b[col]), __ldg(&lin2_b[col+1]));
    }
  }
  // builders: per-thread mu/sig weight window (32 cols), fp16 packed
  int w = bt & 7;                 // column window
  int rgrp = bt >> 3;             // row group (0..15)
  __half2 mwc[16], swc[16];
  if (!isg){
    #pragma unroll
    for (int q = 0; q < 16; q++){
      int col = w*32 + q*2;
      mwc[q] = __floats2half2_rn(__ldg(&mu_w[col]),  __ldg(&mu_w[col+1]));
      swc[q] = __floats2half2_rn(__ldg(&sig_w[col]), __ldg(&sig_w[col+1]));
    }
    if (tid == 256){ lp[0] = 0.f; lp[1] = 0.f; }
  }
  float mub = mu_b[0], sgb = sig_b[0];

  unsigned h1bs[2] = { (unsigned)__cvta_generic_to_shared(H1a),
                       (unsigned)__cvta_generic_to_shared(H1b) };
  __half* H1p[2] = { H1a, H1b };
  unsigned ysb = (unsigned)__cvta_generic_to_shared(Ys);
  int rA  = (lane & 7) + ((lane >> 3) & 1) * 8;
  int cA  = (lane >> 4) * 8;
  int rB4 = lane & 15;
  int cB4 = (lane >> 4) * 8;

  const __half2 zero2 = __float2half2_rn(0.f);
  const __half2 s01   = __float2half2_rn(0.01f);

  int pstep = gridDim.x;

  // initial Ys prefetch (builders only)
  if (!isg && blockIdx.x < NPAIR){
    const __half* src = g_Yh + (size_t)(blockIdx.x*2)*ADIM*512;
    for (int g = bt; g < 1792; g += 128) cp16(ysb + g*16, src + g*8);
    CP_COMMIT();
  }
  __syncthreads();   // W2s + lp visible to all (only __syncthreads in kernel)

  if (isg){
    // ================= GEMM role =================
    for (int pair = blockIdx.x; pair < NPAIR; pair += pstep){
      #pragma unroll 1
      for (int t = 0; t < 6; t++){
        int buf = t & 1;
        BAR_SYNC(1 + buf, 384);              // H1[buf] ready
        unsigned h1b = h1bs[buf];

        float acc[4][4][4];
        #pragma unroll
        for (int i=0;i<4;i++) for (int j=0;j<4;j++) for (int q=0;q<4;q++) acc[i][j][q]=0.f;

        unsigned a[2][4][4], bq[2][2][4];
        #pragma unroll
        for (int mi = 0; mi < 4; mi++){
          int row = mi*16 + rA;
          ldsm_x4(a[0][mi][0],a[0][mi][1],a[0][mi][2],a[0][mi][3], h1b + (row*264 + cA)*2);
        }
        #pragma unroll
        for (int nj = 0; nj < 2; nj++){
          int row = warp_n*32 + nj*16 + rB4;
          ldsm_x4(bq[0][nj][0],bq[0][nj][1],bq[0][nj][2],bq[0][nj][3],
                  (unsigned)__cvta_generic_to_shared(W2s) + (row*264 + cB4)*2);
        }
        unsigned w2b = (unsigned)__cvta_generic_to_shared(W2s);
        #pragma unroll
        for (int kk = 0; kk < 16; kk++){
          int cb = kk & 1, nb = cb ^ 1;
          if (kk < 15){
            int k1 = (kk+1)*16;
            #pragma unroll
            for (int mi = 0; mi < 4; mi++){
              int row = mi*16 + rA;
              ldsm_x4(a[nb][mi][0],a[nb][mi][1],a[nb][mi][2],a[nb][mi][3],
                      h1b + (row*264 + k1 + cA)*2);
            }
            #pragma unroll
            for (int nj = 0; nj < 2; nj++){
              int row = warp_n*32 + nj*16 + rB4;
              ldsm_x4(bq[nb][nj][0],bq[nb][nj][1],bq[nb][nj][2],bq[nb][nj][3],
                      w2b + (row*264 + k1 + cB4)*2);
            }
          }
          #pragma unroll
          for (int mi = 0; mi < 4; mi++)
            #pragma unroll
            for (int nj = 0; nj < 2; nj++){
              mma16816s(acc[mi][2*nj],   a[cb][mi], bq[cb][nj][0], bq[cb][nj][2]);
              mma16816s(acc[mi][2*nj+1], a[cb][mi], bq[cb][nj][1], bq[cb][nj][3]);
            }
        }
        BAR_SYNC(6, 256);                    // all GEMM done reading H1[buf]

        // store leaky(acc + b2) as fp16 over H1[buf]
        __half* Hd = H1p[buf];
        #pragma unroll
        for (int mi = 0; mi < 4; mi++){
          int row0 = mi*16 + (lane >> 2);
          #pragma unroll
          for (int ni = 0; ni < 4; ni++){
            int col = warp_n*32 + ni*8 + ((lane & 3) << 1);
            float2 bb = __half22float2(b2c[ni]);
            *(__half2*)&Hd[row0*264 + col] =
              __floats2half2_rn(lky(acc[mi][ni][0] + bb.x), lky(acc[mi][ni][1] + bb.y));
            *(__half2*)&Hd[(row0+8)*264 + col] =
              __floats2half2_rn(lky(acc[mi][ni][2] + bb.x), lky(acc[mi][ni][3] + bb.y));
          }
        }
        BAR_ARRIVE(3 + buf, 384);            // acc[buf] ready for builders
      }
    }
  } else {
    // ================= builder role =================
    for (int pair = blockIdx.x; pair < NPAIR; pair += pstep){
      int b0 = pair*2;
      CP_WAIT0();
      BAR_SYNC(5, 128);                      // all builders' Ys writes visible

      #pragma unroll 1
      for (int t = 0; t < 6; t++){
        int buf = t & 1;
        if (t >= 2){
          // dots + heads for chunk c = t-2 (same buf)
          BAR_SYNC(3 + buf, 384);            // acc stored by GEMM
          int c = t - 2;
          int batch = (c >= 3) ? 1 : 0;
          const __half* Hs = H1p[buf];
          float lc = 0.f;
          #pragma unroll
          for (int it = 0; it < 4; it++){
            int m = rgrp + it*16;
            const __half2* hrow = (const __half2*)&Hs[m*264 + w*32];
            float mp = 0.f, sp = 0.f;
            #pragma unroll
            for (int q = 0; q < 16; q++){
              float2 hv = __half22float2(hrow[q]);
              float2 mv = __half22float2(mwc[q]);
              float2 sv = __half22float2(swc[q]);
              mp += hv.x*mv.x + hv.y*mv.y;
              sp += hv.x*sv.x + hv.y*sv.y;
            }
            mp += __shfl_xor_sync(0xffffffffu, mp, 1);
            sp += __shfl_xor_sync(0xffffffffu, sp, 1);
            mp += __shfl_xor_sync(0xffffffffu, mp, 2);
            sp += __shfl_xor_sync(0xffffffffu, sp, 2);
            mp += __shfl_xor_sync(0xffffffffu, mp, 4);
            sp += __shfl_xor_sync(0xffffffffu, sp, 4);
            if (w == 0){
              int e = (c - 3*batch)*64 + m;
              if (e < E_){
                float mu = softplus_(mp + mub);
                float sd = softplus_(sp + sgb);
                float nz = noise[(size_t)(b0+batch)*E_ + e];
                out[(size_t)(b0+batch)*E_ + e] = mu + sd*nz;
                lc += -0.5f*nz*nz - logf(sd);
              }
            }
          }
          if (w == 0 && lc != 0.f) atomicAdd(&lp[batch], lc);
          BAR_SYNC(7, 128);                  // all builders done reading acc[buf]
        }
        // build H1 chunk t into buf
        __half* H1d = H1p[buf];
        #pragma unroll
        for (int it = 0; it < 16; it++){
          int idx = bt + it*128;
          int m  = idx >> 5;
          int c8 = idx & 31;
          int rg = t*64 + m;
          int bsel = (rg >= 192) ? 1 : 0;
          int e = rg - 192*bsel;
          uint4 val;
          if (e < E_){
            int ii = e/13; int r = e - ii*13; int jj = r + (r >= ii ? 1 : 0);
            uint4 ul = *(const uint4*)&Ys[(bsel*ADIM + ii)*512 + c8*8];
            uint4 ur = *(const uint4*)&Ys[(bsel*ADIM + jj)*512 + 256 + c8*8];
            const __half2* l2 = (const __half2*)&ul;
            const __half2* r2 = (const __half2*)&ur;
            __half2 o[4];
            #pragma unroll
            for (int q = 0; q < 4; q++){
              __half2 s = __hadd2(l2[q], r2[q]);
              o[q] = __hadd2(__hmax2(s, zero2), __hmul2(s01, __hmin2(s, zero2)));
            }
            val = *(uint4*)o;
          } else {
            val = make_uint4(0u,0u,0u,0u);
          }
          *(uint4*)&H1d[m*264 + c8*8] = val;
        }
        BAR_ARRIVE(1 + buf, 384);            // H1[buf] ready
      }

      // Ys dead (build of chunk 5 done in all builders after this barrier)
      BAR_SYNC(5, 128);
      {
        int pn = pair + pstep;
        if (pn < NPAIR){
          const __half* src = g_Yh + (size_t)(pn*2)*ADIM*512;
          for (int g = bt; g < 1792; g += 128) cp16(ysb + g*16, src + g*8);
        }
        CP_COMMIT();
      }

      // drain dots for chunks 4 (buf0) and 5 (buf1)
      #pragma unroll
      for (int c = 4; c < 6; c++){
        int buf = c & 1;
        BAR_SYNC(3 + buf, 384);
        const __half* Hs = H1p[buf];
        float lc = 0.f;
        #pragma unroll
        for (int it = 0; it < 4; it++){
          int m = rgrp + it*16;
          const __half2* hrow = (const __half2*)&Hs[m*264 + w*32];
          float mp = 0.f, sp = 0.f;
          #pragma unroll
          for (int q = 0; q < 16; q++){
            float2 hv = __half22float2(hrow[q]);
            float2 mv = __half22float2(mwc[q]);
            float2 sv = __half22float2(swc[q]);
            mp += hv.x*mv.x + hv.y*mv.y;
            sp += hv.x*sv.x + hv.y*sv.y;
          }
          mp += __shfl_xor_sync(0xffffffffu, mp, 1);
          sp += __shfl_xor_sync(0xffffffffu, sp, 1);
          mp += __shfl_xor_sync(0xffffffffu, mp, 2);
          sp += __shfl_xor_sync(0xffffffffu, sp, 2);
          mp += __shfl_xor_sync(0xffffffffu, mp, 4);
          sp += __shfl_xor_sync(0xffffffffu, sp, 4);
          if (w == 0){
            int e = (c - 3)*64 + m;
            if (e < E_){
              float mu = softplus_(mp + mub);
              float sd = softplus_(sp + sgb);
              float nz = noise[(size_t)(b0+1)*E_ + e];
              out[(size_t)(b0+1)*E_ + e] = mu + sd*nz;
              lc += -0.5f*nz*nz - logf(sd);
            }
          }
        }
        if (w == 0 && lc != 0.f) atomicAdd(&lp[1], lc);
      }
      BAR_SYNC(7, 128);                      // all atomics done
      if (bt == 0){
        out[(size_t)NROWS + b0]     = lp[0] - (float)E_ * 0.91893853320467274f;
        out[(size_t)NROWS + b0 + 1] = lp[1] - (float)E_ * 0.91893853320467274f;
        lp[0] = 0.f; lp[1] = 0.f;
      }
      BAR_SYNC(7, 128);                      // reset visible before next pair
    }
  }
}

// ---------------- host launcher ----------------
extern "C" void kernel_launch(void* const* d_in, const int* in_sizes, int n_in,
                              void* d_out, int out_size){
  const float* state  = (const float*)d_in[0];
  const float* conv_w = (const float*)d_in[1];
  const float* conv_b = (const float*)d_in[2];
  const float* lin1_w = (const float*)d_in[3];
  const float* lin1_b = (const float*)d_in[4];
  const float* lin2_w = (const float*)d_in[5];
  const float* lin2_b = (const float*)d_in[6];
  const float* mu_w   = (const float*)d_in[7];
  const float* mu_b   = (const float*)d_in[8];
  const float* sig_w  = (const float*)d_in[9];
  const float* sig_b  = (const float*)d_in[10];
  const float* noise  = (const float*)d_in[11];
  float* out = (float*)d_out;

  const int SM1 = (128*129 + 8*128 + 8*128) * 4;               // 74240
  const int SM2 = 2 * 128*136 * 2;                             // 69632
  const int SM3 = (14336 + 256*264 + 2*64*264) * 2 + 16;       // 231440

  cudaFuncSetAttribute(k1_build, cudaFuncAttributeMaxDynamicSharedMemorySize, SM1);
  cudaFuncSetAttribute(k2_ygemm, cudaFuncAttributeMaxDynamicSharedMemorySize, SM2);
  cudaFuncSetAttribute(k3_main,  cudaFuncAttributeMaxDynamicSharedMemorySize, SM3);

  k_prep<<<256, 256>>>(lin1_w, lin2_w);
  k1_build<<<256, 256, SM1>>>(state, conv_w, conv_b);
  k2_ygemm<<<dim3(224, 4), 256, SM2>>>(lin1_b);
  k3_main<<<152, 384, SM3>>>(lin2_b, mu_w, mu_b, sig_w, sig_b, noise, out);
}

// round 14
// speedup vs baseline: 1.0572x; 1.0572x over previous
#include <cuda_runtime.h>
#include <cuda_fp16.h>
#include <cstdint>

#define B_      2048
#define ADIM    14
#define C_      128
#define H_      256
#define E_      182
#define NNODES  (B_*ADIM)   /* 28672 */
#define NROWS   (B_*E_)     /* 372736 */
#define NPAIR   (B_/2)      /* 1024 */

// ---------------- device scratch (no allocs allowed) ----------------
__device__ __align__(16) __half g_W2h [H_*H_];        // lin2_w fp16, row-major (g, h)
__device__ __align__(16) __half g_Wcat[512*C_];       // [W_left rows | W_right rows], k-contig
__device__ __align__(16) __half g_Xh  [NNODES*C_];    // x = g + state, fp16
__device__ __align__(16) __half g_Yh  [(size_t)NNODES*512]; // [yl(256,+b1) | yr(256)] fp16

// ---------------- mma / barrier helpers ----------------
__device__ __forceinline__ void ldsm_x4(unsigned &r0,unsigned &r1,unsigned &r2,unsigned &r3, unsigned a){
  asm volatile("ldmatrix.sync.aligned.m8n8.x4.shared.b16 {%0,%1,%2,%3},[%4];"
    :"=r"(r0),"=r"(r1),"=r"(r2),"=r"(r3):"r"(a));
}
__device__ __forceinline__ void ldsm_x2(unsigned &r0,unsigned &r1, unsigned a){
  asm volatile("ldmatrix.sync.aligned.m8n8.x2.shared.b16 {%0,%1},[%2];"
    :"=r"(r0),"=r"(r1):"r"(a));
}
__device__ __forceinline__ void mma16816(float c[4], const unsigned a[4], const unsigned b[2]){
  asm volatile("mma.sync.aligned.m16n8k16.row.col.f32.f16.f16.f32 "
    "{%0,%1,%2,%3},{%4,%5,%6,%7},{%8,%9},{%0,%1,%2,%3};"
    :"+f"(c[0]),"+f"(c[1]),"+f"(c[2]),"+f"(c[3])
    :"r"(a[0]),"r"(a[1]),"r"(a[2]),"r"(a[3]),"r"(b[0]),"r"(b[1]));
}
__device__ __forceinline__ void mma16816s(float c[4], const unsigned a[4], unsigned b0, unsigned b1){
  asm volatile("mma.sync.aligned.m16n8k16.row.col.f32.f16.f16.f32 "
    "{%0,%1,%2,%3},{%4,%5,%6,%7},{%8,%9},{%0,%1,%2,%3};"
    :"+f"(c[0]),"+f"(c[1]),"+f"(c[2]),"+f"(c[3])
    :"r"(a[0]),"r"(a[1]),"r"(a[2]),"r"(a[3]),"r"(b0),"r"(b1));
}
__device__ __forceinline__ void cp16(unsigned dst, const void* src){
  asm volatile("cp.async.cg.shared.global [%0], [%1], 16;" :: "r"(dst), "l"(src));
}
#define CP_COMMIT() asm volatile("cp.async.commit_group;" ::: "memory")
#define CP_WAIT0()  asm volatile("cp.async.wait_group 0;" ::: "memory")
#define BAR_SYNC(id, n)   asm volatile("bar.sync %0, %1;"   :: "r"(id), "r"(n) : "memory")
#define BAR_ARRIVE(id, n) asm volatile("bar.arrive %0, %1;" :: "r"(id), "r"(n) : "memory")

__device__ __forceinline__ float lky(float v){ return v > 0.f ? v : 0.01f*v; }
__device__ __forceinline__ float softplus_(float x){ return fmaxf(x,0.f) + log1pf(expf(-fabsf(x))); }

// ---------------- K0: weight conversion ----------------
__global__ void k_prep(const float* __restrict__ lin1_w, const float* __restrict__ lin2_w){
  int i = blockIdx.x*blockDim.x + threadIdx.x;   // 65536 threads
  if (i < H_*H_) g_W2h[i] = __float2half(lin2_w[i]);
  if (i < 512*C_){
    int o = i >> 7, c = i & 127;
    float v = (o < H_) ? lin1_w[o*(2*C_) + c] : lin1_w[(o-H_)*(2*C_) + C_ + c];
    g_Wcat[i] = __float2half(v);
  }
}

// ---------------- K1: s_bar -> g -> X (8 batches per block) ----------------
__global__ __launch_bounds__(256,1)
void k1_build(const float* __restrict__ state, const float* __restrict__ conv_w,
              const float* __restrict__ conv_b){
  extern __shared__ float sm1[];
  float* cw   = sm1;                 // 128 x 129
  float* sbar = cw + 128*129;        // 8 x 128
  float* gg   = sbar + 8*128;        // 8 x 128
  int tid = threadIdx.x;
  int b0  = blockIdx.x * 8;

  for (int i = tid; i < 128*128; i += 256){ int r = i>>7, c = i&127; cw[r*129+c] = conv_w[i]; }
  for (int idx = tid; idx < 8*128; idx += 256){
    int bb = idx >> 7, c = idx & 127;
    const float* sp = state + (size_t)(b0+bb)*ADIM*C_ + c;
    float s = 0.f;
    #pragma unroll
    for (int i = 0; i < ADIM; i++) s += sp[i*C_];
    sbar[idx] = s * (1.0f/14.0f);
  }
  __syncthreads();
  #pragma unroll
  for (int u = 0; u < 4; u++){
    int o = tid + u*256;
    int bb = o >> 7, h = o & 127;
    const float* sb = sbar + bb*128;
    const float* w  = cw + h*129;
    float acc = 0.f;
    #pragma unroll 8
    for (int c = 0; c < 128; c++) acc += sb[c]*w[c];
    gg[o] = fmaxf(acc + conv_b[h], 0.f);
  }
  __syncthreads();
  for (int idx = tid; idx < 8*ADIM*C_; idx += 256){
    int bb = idx / (ADIM*C_); int rem = idx - bb*(ADIM*C_);
    int c  = rem & 127;
    size_t node = (size_t)(b0+bb)*ADIM + (rem >> 7);
    g_Xh[node*C_ + c] = __float2half(gg[bb*128 + c] + state[node*C_ + c]);
  }
}

// ---------------- K2: Y = X @ Wcat^T, fp16 out, b1 folded ----------------
__global__ __launch_bounds__(256,1)
void k2_ygemm(const float* __restrict__ lin1_b){
  extern __shared__ __half sm2[];
  __half* As = sm2;             // 128 x 136
  __half* Bs = As + 128*136;    // 128 x 136
  int tid = threadIdx.x;
  int m0 = blockIdx.x * 128, n0 = blockIdx.y * 128;

  for (int idx = tid; idx < 128*16; idx += 256){
    int r = idx >> 4, c = idx & 15;
    *(uint4*)&As[r*136 + c*8] = *(const uint4*)&g_Xh [(size_t)(m0+r)*C_ + c*8];
    *(uint4*)&Bs[r*136 + c*8] = *(const uint4*)&g_Wcat[(size_t)(n0+r)*C_ + c*8];
  }
  __syncthreads();

  int lane = tid & 31, warp = tid >> 5, wm = warp >> 2, wn = warp & 3;
  unsigned abase = (unsigned)__cvta_generic_to_shared(As);
  unsigned bbase = (unsigned)__cvta_generic_to_shared(Bs);
  float acc[4][4][4];
  #pragma unroll
  for (int i=0;i<4;i++) for (int j=0;j<4;j++) for (int q=0;q<4;q++) acc[i][j][q]=0.f;

  int rA = (lane & 7) + ((lane >> 3) & 1) * 8;
  int cA = (lane >> 4) * 8;
  int l16 = lane & 15;
  int rB = l16 & 7;
  int cB = (l16 >> 3) * 8;

  #pragma unroll
  for (int kk = 0; kk < 8; kk++){
    int k0 = kk*16;
    unsigned a[4][4], b[4][2];
    #pragma unroll
    for (int mi = 0; mi < 4; mi++){
      int row = wm*64 + mi*16 + rA;
      ldsm_x4(a[mi][0],a[mi][1],a[mi][2],a[mi][3], abase + (row*136 + k0 + cA)*2);
    }
    #pragma unroll
    for (int ni = 0; ni < 4; ni++){
      int row = wn*32 + ni*8 + rB;
      ldsm_x2(b[ni][0],b[ni][1], bbase + (row*136 + k0 + cB)*2);
    }
    #pragma unroll
    for (int mi = 0; mi < 4; mi++)
      #pragma unroll
      for (int ni = 0; ni < 4; ni++)
        mma16816(acc[mi][ni], a[mi], b[ni]);
  }
  bool leftblk = (n0 < 256);
  #pragma unroll
  for (int ni = 0; ni < 4; ni++){
    int col = n0 + wn*32 + ni*8 + ((lane & 3) << 1);
    float a0 = leftblk ? __ldg(&lin1_b[col])   : 0.f;
    float a1 = leftblk ? __ldg(&lin1_b[col+1]) : 0.f;
    #pragma unroll
    for (int mi = 0; mi < 4; mi++){
      int row = m0 + wm*64 + mi*16 + (lane >> 2);
      *(__half2*)&g_Yh[(size_t)row*512 + col] =
        __floats2half2_rn(acc[mi][ni][0] + a0, acc[mi][ni][1] + a1);
      *(__half2*)&g_Yh[(size_t)(row+8)*512 + col] =
        __floats2half2_rn(acc[mi][ni][2] + a0, acc[mi][ni][3] + a1);
    }
  }
}

// ---------------- K3: warp-specialized GEMM + builder mma heads ----------------
// 384 threads: warps 0-7 = GEMM (m48 x n32, 1m x 8n, chunk M=48, 8 chunks/pair),
// warps 8-11 = builders: H1 build; warps 8-10 also head-mma (m16 each) + heads.
// Lifecycle per H1[buf]: build -> [ready] -> GEMM k-loop -> [id6 GEMM-only]
//   -> GEMM STS lky(acc+b2) fp16 over H1 -> [accready] -> builder head-mma+heads
//   -> [id7 builder-only] -> build next chunk in same buf.
// Barriers: ready=1,2  accready=3,4  Ys-guard=5(128)  gemm=6(256)  builder=7(128).
__global__ __launch_bounds__(384,1)
void k3_main(const float* __restrict__ lin2_b,
             const float* __restrict__ mu_w,  const float* __restrict__ mu_b,
             const float* __restrict__ sig_w, const float* __restrict__ sig_b,
             const float* __restrict__ noise, float* __restrict__ out){
  extern __shared__ __half sm3[];
  __half* Ys  = sm3;                 // 2 x 14 x 512 = 14336 halves
  __half* W2s = Ys + 14336;          // 256 x 264 = 67584
  __half* H1a = W2s + 67584;         // 48 x 264 = 12672
  __half* H1b = H1a + 12672;         // 48 x 264
  __half* WH  = H1b + 12672;         // 8 x 264 (row0=mu_w, row1=sig_w, rows2-7=0)
  float*  lp  = (float*)(WH + 2112); // 2 floats (+pad) -> total 218768 B

  int tid  = threadIdx.x;
  int lane = tid & 31, warp = tid >> 5;          // 12 warps
  bool isg = (warp < 8);
  int warp_n = warp & 7;
  int bt = tid & 127;                             // builder-local index
  int bwarp = warp - 8;                           // 0..3 for builders

  // one-time: W2 into smem (stride 264)
  for (int idx = tid; idx < 256*32; idx += 384){
    int r = idx >> 5, c = idx & 31;
    *(uint4*)&W2s[r*264 + c*8] = ((const uint4*)g_W2h)[r*32 + c];
  }
  // WH: zero 8x264, then rows 0/1 = mu_w/sig_w
  for (int idx = tid; idx < 8*264; idx += 384) WH[idx] = __float2half(0.f);
  __syncthreads();
  if (tid < 256){
    WH[tid]       = __float2half(__ldg(&mu_w[tid]));
    WH[264 + tid] = __float2half(__ldg(&sig_w[tid]));
  }
  // GEMM: per-thread b2 constants (n32 slice)
  __half2 b2c[4];
  if (isg){
    #pragma unroll
    for (int ni = 0; ni < 4; ni++){
      int col = warp_n*32 + ni*8 + ((lane & 3) << 1);
      b2c[ni] = __floats2half2_rn(__ldg(&lin2_b[col]), __ldg(&lin2_b[col+1]));
    }
  }
  if (tid == 256){ lp[0] = 0.f; lp[1] = 0.f; }
  float mub = mu_b[0], sgb = sig_b[0];

  unsigned h1bs[2] = { (unsigned)__cvta_generic_to_shared(H1a),
                       (unsigned)__cvta_generic_to_shared(H1b) };
  __half* H1p[2] = { H1a, H1b };
  unsigned ysb = (unsigned)__cvta_generic_to_shared(Ys);
  unsigned w2b = (unsigned)__cvta_generic_to_shared(W2s);
  unsigned whb = (unsigned)__cvta_generic_to_shared(WH);
  int rA  = (lane & 7) + ((lane >> 3) & 1) * 8;
  int cA  = (lane >> 4) * 8;
  int l16 = lane & 15;
  int rBo = l16 & 7;
  int cB  = (l16 >> 3) * 8;

  const __half2 zero2 = __float2half2_rn(0.f);
  const __half2 s01   = __float2half2_rn(0.01f);

  int pstep = gridDim.x;

  // initial Ys prefetch (builders only)
  if (!isg && blockIdx.x < NPAIR){
    const __half* src = g_Yh + (size_t)(blockIdx.x*2)*ADIM*512;
    for (int g = bt; g < 1792; g += 128) cp16(ysb + g*16, src + g*8);
    CP_COMMIT();
  }
  __syncthreads();   // smem consts visible to all

  if (isg){
    // ================= GEMM role =================
    for (int pair = blockIdx.x; pair < NPAIR; pair += pstep){
      #pragma unroll 1
      for (int t = 0; t < 8; t++){
        int buf = t & 1;
        BAR_SYNC(1 + buf, 384);              // H1[buf] ready
        unsigned h1b = h1bs[buf];

        float acc[3][4][4];
        #pragma unroll
        for (int i=0;i<3;i++) for (int j=0;j<4;j++) for (int q=0;q<4;q++) acc[i][j][q]=0.f;

        unsigned a[2][3][4], bq[2][2][4];
        #pragma unroll
        for (int mi = 0; mi < 3; mi++){
          int row = mi*16 + rA;
          ldsm_x4(a[0][mi][0],a[0][mi][1],a[0][mi][2],a[0][mi][3], h1b + (row*264 + cA)*2);
        }
        #pragma unroll
        for (int nj = 0; nj < 2; nj++){
          int row = warp_n*32 + nj*16 + (lane & 15);
          ldsm_x4(bq[0][nj][0],bq[0][nj][1],bq[0][nj][2],bq[0][nj][3],
                  w2b + (row*264 + cA)*2);
        }
        #pragma unroll
        for (int kk = 0; kk < 16; kk++){
          int cb = kk & 1, nb = cb ^ 1;
          if (kk < 15){
            int k1 = (kk+1)*16;
            #pragma unroll
            for (int mi = 0; mi < 3; mi++){
              int row = mi*16 + rA;
              ldsm_x4(a[nb][mi][0],a[nb][mi][1],a[nb][mi][2],a[nb][mi][3],
                      h1b + (row*264 + k1 + cA)*2);
            }
            #pragma unroll
            for (int nj = 0; nj < 2; nj++){
              int row = warp_n*32 + nj*16 + (lane & 15);
              ldsm_x4(bq[nb][nj][0],bq[nb][nj][1],bq[nb][nj][2],bq[nb][nj][3],
                      w2b + (row*264 + k1 + cA)*2);
            }
          }
          #pragma unroll
          for (int mi = 0; mi < 3; mi++)
            #pragma unroll
            for (int nj = 0; nj < 2; nj++){
              mma16816s(acc[mi][2*nj],   a[cb][mi], bq[cb][nj][0], bq[cb][nj][2]);
              mma16816s(acc[mi][2*nj+1], a[cb][mi], bq[cb][nj][1], bq[cb][nj][3]);
            }
        }
        BAR_SYNC(6, 256);                    // all GEMM done reading H1[buf]

        // store lky(acc + b2) as fp16 over H1[buf]
        __half* Hd = H1p[buf];
        #pragma unroll
        for (int mi = 0; mi < 3; mi++){
          int row0 = mi*16 + (lane >> 2);
          #pragma unroll
          for (int ni = 0; ni < 4; ni++){
            int col = warp_n*32 + ni*8 + ((lane & 3) << 1);
            float2 bb = __half22float2(b2c[ni]);
            *(__half2*)&Hd[row0*264 + col] =
              __floats2half2_rn(lky(acc[mi][ni][0] + bb.x), lky(acc[mi][ni][1] + bb.y));
            *(__half2*)&Hd[(row0+8)*264 + col] =
              __floats2half2_rn(lky(acc[mi][ni][2] + bb.x), lky(acc[mi][ni][3] + bb.y));
          }
        }
        BAR_ARRIVE(3 + buf, 384);            // acc[buf] ready for builders
      }
    }
  } else {
    // ================= builder role =================
    for (int pair = blockIdx.x; pair < NPAIR; pair += pstep){
      int b0 = pair*2;
      CP_WAIT0();
      BAR_SYNC(5, 128);                      // all builders' Ys writes visible

      #pragma unroll 1
      for (int t = 0; t < 10; t++){
        int buf = t & 1;
        if (t >= 2){
          // heads for chunk c = t-2 (H values in H1[buf])
          BAR_SYNC(3 + buf, 384);
          int c = t - 2;
          if (bwarp < 3){
            unsigned h1b = h1bs[buf];
            float dc[4] = {0.f, 0.f, 0.f, 0.f};
            #pragma unroll
            for (int kk = 0; kk < 16; kk++){
              int k0 = kk*16;
              unsigned av[4], bv[2];
              ldsm_x4(av[0],av[1],av[2],av[3],
                      h1b + ((bwarp*16 + rA)*264 + k0 + cA)*2);
              ldsm_x2(bv[0],bv[1], whb + (rBo*264 + k0 + cB)*2);
              mma16816(dc, av, bv);
            }
            if ((lane & 3) == 0){
              int batch = (c >= 4) ? 1 : 0;
              float lc = 0.f;
              #pragma unroll
              for (int h = 0; h < 2; h++){
                int m = bwarp*16 + (lane >> 2) + h*8;
                int e = (c - 4*batch)*48 + m;
                float pm = (h == 0) ? dc[0] : dc[2];
                float ps = (h == 0) ? dc[1] : dc[3];
                if (e < E_){
                  float mu = softplus_(pm + mub);
                  float sd = softplus_(ps + sgb);
                  float nz = noise[(size_t)(b0+batch)*E_ + e];
                  out[(size_t)(b0+batch)*E_ + e] = mu + sd*nz;
                  lc += -0.5f*nz*nz - logf(sd);
                }
              }
              if (lc != 0.f) atomicAdd(&lp[batch], lc);
            }
          }
          BAR_SYNC(7, 128);                  // builders done reading H1[buf]
        }
        if (t < 8){
          // build H1 chunk t into buf
          __half* H1d = H1p[buf];
          #pragma unroll
          for (int it = 0; it < 12; it++){
            int idx = bt + it*128;           // 48*32 entries
            int m  = idx >> 5;
            int c8 = idx & 31;
            int rg = t*48 + m;               // 0..383
            int bsel = (rg >= 192) ? 1 : 0;
            int e = rg - 192*bsel;
            uint4 val;
            if (e < E_){
              int ii = e/13; int r = e - ii*13; int jj = r + (r >= ii ? 1 : 0);
              uint4 ul = *(const uint4*)&Ys[(bsel*ADIM + ii)*512 + c8*8];
              uint4 ur = *(const uint4*)&Ys[(bsel*ADIM + jj)*512 + 256 + c8*8];
              const __half2* l2 = (const __half2*)&ul;
              const __half2* r2 = (const __half2*)&ur;
              __half2 o[4];
              #pragma unroll
              for (int q = 0; q < 4; q++){
                __half2 s = __hadd2(l2[q], r2[q]);
                o[q] = __hadd2(__hmax2(s, zero2), __hmul2(s01, __hmin2(s, zero2)));
              }
              val = *(uint4*)o;
            } else {
              val = make_uint4(0u,0u,0u,0u);
            }
            *(uint4*)&H1d[m*264 + c8*8] = val;
          }
          BAR_ARRIVE(1 + buf, 384);          // H1[buf] ready
          if (t == 7){
            // Ys dead after all builds: prefetch next pair
            BAR_SYNC(5, 128);
            int pn = pair + pstep;
            if (pn < NPAIR){
              const __half* src = g_Yh + (size_t)(pn*2)*ADIM*512;
              for (int g = bt; g < 1792; g += 128) cp16(ysb + g*16, src + g*8);
            }
            CP_COMMIT();
          }
        }
      }
      // log-prob writeout (all head atomics done after t=9's BAR_SYNC(7))
      if (bt == 0){
        out[(size_t)NROWS + b0]     = lp[0] - (float)E_ * 0.91893853320467274f;
        out[(size_t)NROWS + b0 + 1] = lp[1] - (float)E_ * 0.91893853320467274f;
        lp[0] = 0.f; lp[1] = 0.f;
      }
      BAR_SYNC(7, 128);                      // reset visible before next pair
    }
  }
}

// ---------------- host launcher ----------------
extern "C" void kernel_launch(void* const* d_in, const int* in_sizes, int n_in,
                              void* d_out, int out_size){
  const float* state  = (const float*)d_in[0];
  const float* conv_w = (const float*)d_in[1];
  const float* conv_b = (const float*)d_in[2];
  const float* lin1_w = (const float*)d_in[3];
  const float* lin1_b = (const float*)d_in[4];
  const float* lin2_w = (const float*)d_in[5];
  const float* lin2_b = (const float*)d_in[6];
  const float* mu_w   = (const float*)d_in[7];
  const float* mu_b   = (const float*)d_in[8];
  const float* sig_w  = (const float*)d_in[9];
  const float* sig_b  = (const float*)d_in[10];
  const float* noise  = (const float*)d_in[11];
  float* out = (float*)d_out;

  const int SM1 = (128*129 + 8*128 + 8*128) * 4;                     // 74240
  const int SM2 = 2 * 128*136 * 2;                                   // 69632
  const int SM3 = (14336 + 67584 + 2*12672 + 2112) * 2 + 16;         // 218768

  cudaFuncSetAttribute(k1_build, cudaFuncAttributeMaxDynamicSharedMemorySize, SM1);
  cudaFuncSetAttribute(k2_ygemm, cudaFuncAttributeMaxDynamicSharedMemorySize, SM2);
  cudaFuncSetAttribute(k3_main,  cudaFuncAttributeMaxDynamicSharedMemorySize, SM3);

  k_prep<<<256, 256>>>(lin1_w, lin2_w);
  k1_build<<<256, 256, SM1>>>(state, conv_w, conv_b);
  k2_ygemm<<<dim3(224, 4), 256, SM2>>>(lin1_b);
  k3_main<<<152, 384, SM3>>>(lin2_b, mu_w, mu_b, sig_w, sig_b, noise, out);
}

// round 15
// speedup vs baseline: 1.2978x; 1.2276x over previous
#include <cuda_runtime.h>
#include <cuda_fp16.h>
#include <cstdint>

#define B_      2048
#define ADIM    14
#define C_      128
#define H_      256
#define E_      182
#define NNODES  (B_*ADIM)   /* 28672 */
#define NROWS   (B_*E_)     /* 372736 */
#define NPAIR   (B_/2)      /* 1024 */

// ---------------- device scratch (no allocs allowed) ----------------
__device__ __align__(16) __half g_W2h [H_*H_];        // lin2_w fp16, row-major (g, h)
__device__ __align__(16) __half g_Wcat[512*C_];       // [W_left rows | W_right rows], k-contig
__device__ __align__(16) __half g_Xh  [NNODES*C_];    // x = g + state, fp16
__device__ __align__(16) __half g_Yh  [(size_t)NNODES*512]; // [yl(256,+b1) | yr(256)] fp16
__device__ __align__(16) float2 g_part[(size_t)NPAIR*384*8]; // (pm,ps) per (pair,row,ngroup)

// ---------------- mma / barrier helpers ----------------
__device__ __forceinline__ void ldsm_x4(unsigned &r0,unsigned &r1,unsigned &r2,unsigned &r3, unsigned a){
  asm volatile("ldmatrix.sync.aligned.m8n8.x4.shared.b16 {%0,%1,%2,%3},[%4];"
    :"=r"(r0),"=r"(r1),"=r"(r2),"=r"(r3):"r"(a));
}
__device__ __forceinline__ void ldsm_x2(unsigned &r0,unsigned &r1, unsigned a){
  asm volatile("ldmatrix.sync.aligned.m8n8.x2.shared.b16 {%0,%1},[%2];"
    :"=r"(r0),"=r"(r1):"r"(a));
}
__device__ __forceinline__ void mma16816(float c[4], const unsigned a[4], const unsigned b[2]){
  asm volatile("mma.sync.aligned.m16n8k16.row.col.f32.f16.f16.f32 "
    "{%0,%1,%2,%3},{%4,%5,%6,%7},{%8,%9},{%0,%1,%2,%3};"
    :"+f"(c[0]),"+f"(c[1]),"+f"(c[2]),"+f"(c[3])
    :"r"(a[0]),"r"(a[1]),"r"(a[2]),"r"(a[3]),"r"(b[0]),"r"(b[1]));
}
__device__ __forceinline__ void mma16816s(float c[4], const unsigned a[4], unsigned b0, unsigned b1){
  asm volatile("mma.sync.aligned.m16n8k16.row.col.f32.f16.f16.f32 "
    "{%0,%1,%2,%3},{%4,%5,%6,%7},{%8,%9},{%0,%1,%2,%3};"
    :"+f"(c[0]),"+f"(c[1]),"+f"(c[2]),"+f"(c[3])
    :"r"(a[0]),"r"(a[1]),"r"(a[2]),"r"(a[3]),"r"(b0),"r"(b1));
}
__device__ __forceinline__ void cp16(unsigned dst, const void* src){
  asm volatile("cp.async.cg.shared.global [%0], [%1], 16;" :: "r"(dst), "l"(src));
}
#define CP_COMMIT() asm volatile("cp.async.commit_group;" ::: "memory")
#define CP_WAIT0()  asm volatile("cp.async.wait_group 0;" ::: "memory")
#define BAR_SYNC(id, n)   asm volatile("bar.sync %0, %1;"   :: "r"(id), "r"(n) : "memory")
#define BAR_ARRIVE(id, n) asm volatile("bar.arrive %0, %1;" :: "r"(id), "r"(n) : "memory")

__device__ __forceinline__ float lky(float v){ return v > 0.f ? v : 0.01f*v; }
__device__ __forceinline__ float softplus_(float x){ return fmaxf(x,0.f) + log1pf(expf(-fabsf(x))); }

// ---------------- K1: (fused k_prep) weights + s_bar -> g -> X ----------------
__global__ __launch_bounds__(256,1)
void k1_build(const float* __restrict__ state, const float* __restrict__ conv_w,
              const float* __restrict__ conv_b,
              const float* __restrict__ lin1_w, const float* __restrict__ lin2_w){
  // fused weight conversion (grid is 256x256 = 65536 threads, same as old k_prep)
  {
    int i = blockIdx.x*blockDim.x + threadIdx.x;
    if (i < H_*H_) g_W2h[i] = __float2half(lin2_w[i]);
    if (i < 512*C_){
      int o = i >> 7, c = i & 127;
      float v = (o < H_) ? lin1_w[o*(2*C_) + c] : lin1_w[(o-H_)*(2*C_) + C_ + c];
      g_Wcat[i] = __float2half(v);
    }
  }
  extern __shared__ float sm1[];
  float* cw   = sm1;                 // 128 x 129
  float* sbar = cw + 128*129;        // 8 x 128
  float* gg   = sbar + 8*128;        // 8 x 128
  int tid = threadIdx.x;
  int b0  = blockIdx.x * 8;

  for (int i = tid; i < 128*128; i += 256){ int r = i>>7, c = i&127; cw[r*129+c] = conv_w[i]; }
  for (int idx = tid; idx < 8*128; idx += 256){
    int bb = idx >> 7, c = idx & 127;
    const float* sp = state + (size_t)(b0+bb)*ADIM*C_ + c;
    float s = 0.f;
    #pragma unroll
    for (int i = 0; i < ADIM; i++) s += sp[i*C_];
    sbar[idx] = s * (1.0f/14.0f);
  }
  __syncthreads();
  #pragma unroll
  for (int u = 0; u < 4; u++){
    int o = tid + u*256;
    int bb = o >> 7, h = o & 127;
    const float* sb = sbar + bb*128;
    const float* w  = cw + h*129;
    float acc = 0.f;
    #pragma unroll 8
    for (int c = 0; c < 128; c++) acc += sb[c]*w[c];
    gg[o] = fmaxf(acc + conv_b[h], 0.f);
  }
  __syncthreads();
  for (int idx = tid; idx < 8*ADIM*C_; idx += 256){
    int bb = idx / (ADIM*C_); int rem = idx - bb*(ADIM*C_);
    int c  = rem & 127;
    size_t node = (size_t)(b0+bb)*ADIM + (rem >> 7);
    g_Xh[node*C_ + c] = __float2half(gg[bb*128 + c] + state[node*C_ + c]);
  }
}

// ---------------- K2: Y = X @ Wcat^T, fp16 out, b1 folded ----------------
__global__ __launch_bounds__(256,1)
void k2_ygemm(const float* __restrict__ lin1_b){
  extern __shared__ __half sm2[];
  __half* As = sm2;             // 128 x 136
  __half* Bs = As + 128*136;    // 128 x 136
  int tid = threadIdx.x;
  int m0 = blockIdx.x * 128, n0 = blockIdx.y * 128;

  for (int idx = tid; idx < 128*16; idx += 256){
    int r = idx >> 4, c = idx & 15;
    *(uint4*)&As[r*136 + c*8] = *(const uint4*)&g_Xh [(size_t)(m0+r)*C_ + c*8];
    *(uint4*)&Bs[r*136 + c*8] = *(const uint4*)&g_Wcat[(size_t)(n0+r)*C_ + c*8];
  }
  __syncthreads();

  int lane = tid & 31, warp = tid >> 5, wm = warp >> 2, wn = warp & 3;
  unsigned abase = (unsigned)__cvta_generic_to_shared(As);
  unsigned bbase = (unsigned)__cvta_generic_to_shared(Bs);
  float acc[4][4][4];
  #pragma unroll
  for (int i=0;i<4;i++) for (int j=0;j<4;j++) for (int q=0;q<4;q++) acc[i][j][q]=0.f;

  int rA = (lane & 7) + ((lane >> 3) & 1) * 8;
  int cA = (lane >> 4) * 8;
  int l16 = lane & 15;
  int rB = l16 & 7;
  int cB = (l16 >> 3) * 8;

  #pragma unroll
  for (int kk = 0; kk < 8; kk++){
    int k0 = kk*16;
    unsigned a[4][4], b[4][2];
    #pragma unroll
    for (int mi = 0; mi < 4; mi++){
      int row = wm*64 + mi*16 + rA;
      ldsm_x4(a[mi][0],a[mi][1],a[mi][2],a[mi][3], abase + (row*136 + k0 + cA)*2);
    }
    #pragma unroll
    for (int ni = 0; ni < 4; ni++){
      int row = wn*32 + ni*8 + rB;
      ldsm_x2(b[ni][0],b[ni][1], bbase + (row*136 + k0 + cB)*2);
    }
    #pragma unroll
    for (int mi = 0; mi < 4; mi++)
      #pragma unroll
      for (int ni = 0; ni < 4; ni++)
        mma16816(acc[mi][ni], a[mi], b[ni]);
  }
  bool leftblk = (n0 < 256);
  #pragma unroll
  for (int ni = 0; ni < 4; ni++){
    int col = n0 + wn*32 + ni*8 + ((lane & 3) << 1);
    float a0 = leftblk ? __ldg(&lin1_b[col])   : 0.f;
    float a1 = leftblk ? __ldg(&lin1_b[col+1]) : 0.f;
    #pragma unroll
    for (int mi = 0; mi < 4; mi++){
      int row = m0 + wm*64 + mi*16 + (lane >> 2);
      *(__half2*)&g_Yh[(size_t)row*512 + col] =
        __floats2half2_rn(acc[mi][ni][0] + a0, acc[mi][ni][1] + a1);
      *(__half2*)&g_Yh[(size_t)(row+8)*512 + col] =
        __floats2half2_rn(acc[mi][ni][2] + a0, acc[mi][ni][3] + a1);
    }
  }
}

// ---------------- K3: R10 structure + epilogue-via-mma ----------------
// 384 threads: warps 0-7 = GEMM (m64 x n32, 1m x 8n, chunk M=64, 6 chunks/pair),
// warps 8-11 = builders (H1 double-buffered) + Ys prefetch.
// Barriers: ready=1,2 (builder->gemm); free=3,4 (gemm->builder); Ys-guard=5 (128).
__global__ __launch_bounds__(384,1)
void k3_main(const float* __restrict__ lin2_b,
             const float* __restrict__ mu_w, const float* __restrict__ sig_w){
  extern __shared__ __half sm3[];
  __half* Ys  = sm3;                 // 2 x 14 x 512 = 14336 halves (one pair)
  __half* W2s = Ys + 14336;          // 256 x 264 = 67584
  __half* H1a = W2s + 67584;         // 64 x 264
  __half* H1b = H1a + 16896;         // 64 x 264
  // total (14336 + 67584 + 2*16896)*2 = 231424 B

  int tid  = threadIdx.x;
  int lane = tid & 31, warp = tid >> 5;          // 12 warps
  bool isg = (warp < 8);
  int warp_n = warp & 7;
  int bt = tid & 127;

  // one-time: W2 into smem (stride 264)
  for (int idx = tid; idx < 256*32; idx += 384){
    int r = idx >> 5, c = idx & 31;
    *(uint4*)&W2s[r*264 + c*8] = ((const uint4*)g_W2h)[r*32 + c];
  }
  // GEMM-warp constants: b2 slice + head-weight B-fragments.
  // B frag (k16n8): b0 = (n=lane>>2, k=(lane&3)*2,+1), b1 = same k+8.
  // n=0 -> mu_w, n=1 -> sig_w, n>=2 -> 0. k global = warp_n*32 + frag*16 + ...
  __half2 b2c[4];
  unsigned bw[2][2];
  if (isg){
    #pragma unroll
    for (int ni = 0; ni < 4; ni++){
      int col = warp_n*32 + ni*8 + ((lane & 3) << 1);
      b2c[ni] = __floats2half2_rn(__ldg(&lin2_b[col]), __ldg(&lin2_b[col+1]));
    }
    int hn = lane >> 2;
    const float* wsrc = (hn == 0) ? mu_w : sig_w;
    #pragma unroll
    for (int f = 0; f < 2; f++){
      int kb = warp_n*32 + f*16 + ((lane & 3) << 1);
      __half2 lo = (hn < 2) ? __floats2half2_rn(__ldg(&wsrc[kb]),   __ldg(&wsrc[kb+1]))
                            : __float2half2_rn(0.f);
      __half2 hi = (hn < 2) ? __floats2half2_rn(__ldg(&wsrc[kb+8]), __ldg(&wsrc[kb+9]))
                            : __float2half2_rn(0.f);
      bw[f][0] = *(unsigned*)&lo;
      bw[f][1] = *(unsigned*)&hi;
    }
  }

  unsigned h1bs[2] = { (unsigned)__cvta_generic_to_shared(H1a),
                       (unsigned)__cvta_generic_to_shared(H1b) };
  __half* H1p[2] = { H1a, H1b };
  unsigned ysb = (unsigned)__cvta_generic_to_shared(Ys);
  unsigned w2b = (unsigned)__cvta_generic_to_shared(W2s);
  int rA  = (lane & 7) + ((lane >> 3) & 1) * 8;
  int cA  = (lane >> 4) * 8;
  int rB4 = lane & 15;
  int cB4 = (lane >> 4) * 8;

  const __half2 zero2 = __float2half2_rn(0.f);
  const __half2 s01   = __float2half2_rn(0.01f);

  int pstep = gridDim.x;

  // initial Ys prefetch (builders only)
  if (!isg && blockIdx.x < NPAIR){
    const __half* src = g_Yh + (size_t)(blockIdx.x*2)*ADIM*512;
    for (int g = bt; g < 1792; g += 128) cp16(ysb + g*16, src + g*8);
    CP_COMMIT();
  }
  __syncthreads();   // W2s visible to all

  if (isg){
    // ================= GEMM role =================
    for (int pair = blockIdx.x; pair < NPAIR; pair += pstep){
      #pragma unroll 1
      for (int t = 0; t < 6; t++){
        int buf = t & 1;
        BAR_SYNC(1 + buf, 384);              // H1[buf] ready
        unsigned h1b = h1bs[buf];

        float acc[4][4][4];
        #pragma unroll
        for (int i=0;i<4;i++) for (int j=0;j<4;j++) for (int q=0;q<4;q++) acc[i][j][q]=0.f;

        unsigned a[2][4][4], bq[2][2][4];
        #pragma unroll
        for (int mi = 0; mi < 4; mi++){
          int row = mi*16 + rA;
          ldsm_x4(a[0][mi][0],a[0][mi][1],a[0][mi][2],a[0][mi][3], h1b + (row*264 + cA)*2);
        }
        #pragma unroll
        for (int nj = 0; nj < 2; nj++){
          int row = warp_n*32 + nj*16 + rB4;
          ldsm_x4(bq[0][nj][0],bq[0][nj][1],bq[0][nj][2],bq[0][nj][3], w2b + (row*264 + cB4)*2);
        }
        #pragma unroll
        for (int kk = 0; kk < 16; kk++){
          int cb = kk & 1, nb = cb ^ 1;
          if (kk < 15){
            int k1 = (kk+1)*16;
            #pragma unroll
            for (int mi = 0; mi < 4; mi++){
              int row = mi*16 + rA;
              ldsm_x4(a[nb][mi][0],a[nb][mi][1],a[nb][mi][2],a[nb][mi][3],
                      h1b + (row*264 + k1 + cA)*2);
            }
            #pragma unroll
            for (int nj = 0; nj < 2; nj++){
              int row = warp_n*32 + nj*16 + rB4;
              ldsm_x4(bq[nb][nj][0],bq[nb][nj][1],bq[nb][nj][2],bq[nb][nj][3],
                      w2b + (row*264 + k1 + cB4)*2);
            }
          }
          // bq regs: r0 = n0-7/k0-7, r1 = n8-15/k0-7, r2 = n0-7/k8-15, r3 = n8-15/k8-15
          #pragma unroll
          for (int mi = 0; mi < 4; mi++)
            #pragma unroll
            for (int nj = 0; nj < 2; nj++){
              mma16816s(acc[mi][2*nj],   a[cb][mi], bq[cb][nj][0], bq[cb][nj][2]);
              mma16816s(acc[mi][2*nj+1], a[cb][mi], bq[cb][nj][1], bq[cb][nj][3]);
            }
        }
        BAR_ARRIVE(3 + buf, 384);            // H1[buf] free

        // ---- epilogue via mma: lky(acc+b2) repacked as A-frags, dot [mu;sig] ----
        float2* pbase = g_part + ((size_t)pair*384 + t*64)*8 + warp_n;
        #pragma unroll
        for (int mi = 0; mi < 4; mi++){
          float v[4][4];
          #pragma unroll
          for (int ni = 0; ni < 4; ni++){
            float2 bb = __half22float2(b2c[ni]);
            v[ni][0] = lky(acc[mi][ni][0] + bb.x);
            v[ni][1] = lky(acc[mi][ni][1] + bb.y);
            v[ni][2] = lky(acc[mi][ni][2] + bb.x);
            v[ni][3] = lky(acc[mi][ni][3] + bb.y);
          }
          // A-frag f: k16 = n-cols [f*16, f*16+16) of this warp's n32 slice
          unsigned af[2][4];
          #pragma unroll
          for (int f = 0; f < 2; f++){
            __half2 h0 = __floats2half2_rn(v[2*f][0],   v[2*f][1]);
            __half2 h1 = __floats2half2_rn(v[2*f][2],   v[2*f][3]);
            __half2 h2 = __floats2half2_rn(v[2*f+1][0], v[2*f+1][1]);
            __half2 h3 = __floats2half2_rn(v[2*f+1][2], v[2*f+1][3]);
            af[f][0] = *(unsigned*)&h0;  af[f][1] = *(unsigned*)&h1;
            af[f][2] = *(unsigned*)&h2;  af[f][3] = *(unsigned*)&h3;
          }
          float dc[4] = {0.f, 0.f, 0.f, 0.f};
          mma16816s(dc, af[0], bw[0][0], bw[0][1]);
          mma16816s(dc, af[1], bw[1][0], bw[1][1]);
          if ((lane & 3) == 0){
            int row = mi*16 + (lane >> 2);
            pbase[(size_t)row*8]     = make_float2(dc[0], dc[1]);
            pbase[(size_t)(row+8)*8] = make_float2(dc[2], dc[3]);
          }
        }
      }
    }
  } else {
    // ================= builder role =================
    int gc = 0;
    for (int pair = blockIdx.x; pair < NPAIR; pair += pstep){
      CP_WAIT0();                          // own cp.async groups done
      BAR_SYNC(5, 128);                    // ALL builders' Ys writes visible
      #pragma unroll 1
      for (int t = 0; t < 6; t++){
        int buf = t & 1;
        if (gc >= 2) BAR_SYNC(3 + buf, 384);   // wait GEMM done with H1[buf]
        __half* H1d = H1p[buf];
        #pragma unroll
        for (int it = 0; it < 16; it++){
          int idx = bt + it*128;           // 64*32 entries
          int m  = idx >> 5;
          int c8 = idx & 31;
          int rg = t*64 + m;               // 0..383
          int bsel = (rg >= 192) ? 1 : 0;
          int e = rg - 192*bsel;
          uint4 val;
          if (e < E_){
            int ii = e/13; int r = e - ii*13; int jj = r + (r >= ii ? 1 : 0);
            uint4 ul = *(const uint4*)&Ys[(bsel*ADIM + ii)*512 + c8*8];
            uint4 ur = *(const uint4*)&Ys[(bsel*ADIM + jj)*512 + 256 + c8*8];
            const __half2* l2 = (const __half2*)&ul;
            const __half2* r2 = (const __half2*)&ur;
            __half2 o[4];
            #pragma unroll
            for (int q = 0; q < 4; q++){
              __half2 s = __hadd2(l2[q], r2[q]);
              o[q] = __hadd2(__hmax2(s, zero2), __hmul2(s01, __hmin2(s, zero2)));
            }
            val = *(uint4*)o;
          } else {
            val = make_uint4(0u,0u,0u,0u);
          }
          *(uint4*)&H1d[m*264 + c8*8] = val;
        }
        BAR_ARRIVE(1 + buf, 384);          // H1[buf] ready
        gc++;
      }
      BAR_SYNC(5, 128);                    // all builders done READING Ys
      // Ys dead: prefetch next pair
      int pn = pair + pstep;
      if (pn < NPAIR){
        const __half* src = g_Yh + (size_t)(pn*2)*ADIM*512;
        for (int g = bt; g < 1792; g += 128) cp16(ysb + g*16, src + g*8);
      }
      CP_COMMIT();
    }
  }
}

// ---------------- K4: heads + log-prob from partials ----------------
__global__ __launch_bounds__(192,1)
void k4_heads(const float* __restrict__ mu_b, const float* __restrict__ sig_b,
              const float* __restrict__ noise, float* __restrict__ out){
  __shared__ float wsum[6];
  int b = blockIdx.x;                 // 0..2047
  int tid = threadIdx.x;              // 0..191
  int pair = b >> 1, half = b & 1;
  const float2* src = g_part + ((size_t)pair*384 + half*192 + tid)*8;
  float mp = mu_b[0], sp = sig_b[0];
  #pragma unroll
  for (int q = 0; q < 8; q++){ float2 v = src[q]; mp += v.x; sp += v.y; }
  float c = 0.f;
  if (tid < E_){
    float mu = softplus_(mp);
    float sd = softplus_(sp);
    float nz = noise[(size_t)b*E_ + tid];
    out[(size_t)b*E_ + tid] = mu + sd*nz;
    c = -0.5f*nz*nz - logf(sd);
  }
  c += __shfl_xor_sync(0xffffffffu, c, 1);
  c += __shfl_xor_sync(0xffffffffu, c, 2);
  c += __shfl_xor_sync(0xffffffffu, c, 4);
  c += __shfl_xor_sync(0xffffffffu, c, 8);
  c += __shfl_xor_sync(0xffffffffu, c, 16);
  if ((tid & 31) == 0) wsum[tid >> 5] = c;
  __syncthreads();
  if (tid == 0){
    float s = wsum[0] + wsum[1] + wsum[2] + wsum[3] + wsum[4] + wsum[5];
    out[(size_t)NROWS + b] = s - (float)E_ * 0.91893853320467274f;
  }
}

// ---------------- host launcher ----------------
extern "C" void kernel_launch(void* const* d_in, const int* in_sizes, int n_in,
                              void* d_out, int out_size){
  const float* state  = (const float*)d_in[0];
  const float* conv_w = (const float*)d_in[1];
  const float* conv_b = (const float*)d_in[2];
  const float* lin1_w = (const float*)d_in[3];
  const float* lin1_b = (const float*)d_in[4];
  const float* lin2_w = (const float*)d_in[5];
  const float* lin2_b = (const float*)d_in[6];
  const float* mu_w   = (const float*)d_in[7];
  const float* mu_b   = (const float*)d_in[8];
  const float* sig_w  = (const float*)d_in[9];
  const float* sig_b  = (const float*)d_in[10];
  const float* noise  = (const float*)d_in[11];
  float* out = (float*)d_out;

  const int SM1 = (128*129 + 8*128 + 8*128) * 4;           // 74240
  const int SM2 = 2 * 128*136 * 2;                         // 69632
  const int SM3 = (14336 + 256*264 + 2*64*264) * 2;        // 231424

  cudaFuncSetAttribute(k1_build, cudaFuncAttributeMaxDynamicSharedMemorySize, SM1);
  cudaFuncSetAttribute(k2_ygemm, cudaFuncAttributeMaxDynamicSharedMemorySize, SM2);
  cudaFuncSetAttribute(k3_main,  cudaFuncAttributeMaxDynamicSharedMemorySize, SM3);

  k1_build<<<256, 256, SM1>>>(state, conv_w, conv_b, lin1_w, lin2_w);
  k2_ygemm<<<dim3(224, 4), 256, SM2>>>(lin1_b);
  k3_main<<<152, 384, SM3>>>(lin2_b, mu_w, sig_w);
  k4_heads<<<B_, 192>>>(mu_b, sig_b, noise, out);
}

// round 16
// speedup vs baseline: 1.3193x; 1.0166x over previous
#include <cuda_runtime.h>
#include <cuda_fp16.h>
#include <cstdint>

#define B_      2048
#define ADIM    14
#define C_      128
#define H_      256
#define E_      182
#define NNODES  (B_*ADIM)   /* 28672 */
#define NROWS   (B_*E_)     /* 372736 */
#define NPAIR   (B_/2)      /* 1024 */

// ---------------- device scratch (no allocs allowed) ----------------
__device__ __align__(16) __half g_W2h [H_*H_];        // lin2_w fp16, row-major (g, h)
__device__ __align__(16) __half g_Wcat[512*C_];       // [W_left rows | W_right rows], k-contig
__device__ __align__(16) __half g_Xh  [NNODES*C_];    // x = g + state, fp16
__device__ __align__(16) __half g_Yh  [(size_t)NNODES*512]; // [yl(256,+b1) | yr(256)] fp16
__device__ __align__(16) float2 g_part[(size_t)NPAIR*384*8]; // (pm,ps) per (pair,row,ngroup)

// ---------------- mma / barrier helpers ----------------
__device__ __forceinline__ void ldsm_x4(unsigned &r0,unsigned &r1,unsigned &r2,unsigned &r3, unsigned a){
  asm volatile("ldmatrix.sync.aligned.m8n8.x4.shared.b16 {%0,%1,%2,%3},[%4];"
    :"=r"(r0),"=r"(r1),"=r"(r2),"=r"(r3):"r"(a));
}
__device__ __forceinline__ void ldsm_x2(unsigned &r0,unsigned &r1, unsigned a){
  asm volatile("ldmatrix.sync.aligned.m8n8.x2.shared.b16 {%0,%1},[%2];"
    :"=r"(r0),"=r"(r1):"r"(a));
}
__device__ __forceinline__ void mma16816(float c[4], const unsigned a[4], const unsigned b[2]){
  asm volatile("mma.sync.aligned.m16n8k16.row.col.f32.f16.f16.f32 "
    "{%0,%1,%2,%3},{%4,%5,%6,%7},{%8,%9},{%0,%1,%2,%3};"
    :"+f"(c[0]),"+f"(c[1]),"+f"(c[2]),"+f"(c[3])
    :"r"(a[0]),"r"(a[1]),"r"(a[2]),"r"(a[3]),"r"(b[0]),"r"(b[1]));
}
__device__ __forceinline__ void mma16816s(float c[4], const unsigned a[4], unsigned b0, unsigned b1){
  asm volatile("mma.sync.aligned.m16n8k16.row.col.f32.f16.f16.f32 "
    "{%0,%1,%2,%3},{%4,%5,%6,%7},{%8,%9},{%0,%1,%2,%3};"
    :"+f"(c[0]),"+f"(c[1]),"+f"(c[2]),"+f"(c[3])
    :"r"(a[0]),"r"(a[1]),"r"(a[2]),"r"(a[3]),"r"(b0),"r"(b1));
}
__device__ __forceinline__ void cp16(unsigned dst, const void* src){
  asm volatile("cp.async.cg.shared.global [%0], [%1], 16;" :: "r"(dst), "l"(src));
}
#define CP_COMMIT() asm volatile("cp.async.commit_group;" ::: "memory")
#define CP_WAIT0()  asm volatile("cp.async.wait_group 0;" ::: "memory")
#define BAR_SYNC(id, n)   asm volatile("bar.sync %0, %1;"   :: "r"(id), "r"(n) : "memory")
#define BAR_ARRIVE(id, n) asm volatile("bar.arrive %0, %1;" :: "r"(id), "r"(n) : "memory")

__device__ __forceinline__ float lky(float v){ return v > 0.f ? v : 0.01f*v; }
__device__ __forceinline__ float softplus_(float x){ return fmaxf(x,0.f) + log1pf(expf(-fabsf(x))); }

// ---------------- K1: (fused k_prep) weights + s_bar -> g -> X ----------------
__global__ __launch_bounds__(256,1)
void k1_build(const float* __restrict__ state, const float* __restrict__ conv_w,
              const float* __restrict__ conv_b,
              const float* __restrict__ lin1_w, const float* __restrict__ lin2_w){
  {
    int i = blockIdx.x*blockDim.x + threadIdx.x;
    if (i < H_*H_) g_W2h[i] = __float2half(lin2_w[i]);
    if (i < 512*C_){
      int o = i >> 7, c = i & 127;
      float v = (o < H_) ? lin1_w[o*(2*C_) + c] : lin1_w[(o-H_)*(2*C_) + C_ + c];
      g_Wcat[i] = __float2half(v);
    }
  }
  extern __shared__ float sm1[];
  float* cw   = sm1;                 // 128 x 129
  float* sbar = cw + 128*129;        // 8 x 128
  float* gg   = sbar + 8*128;        // 8 x 128
  int tid = threadIdx.x;
  int b0  = blockIdx.x * 8;

  for (int i = tid; i < 128*128; i += 256){ int r = i>>7, c = i&127; cw[r*129+c] = conv_w[i]; }
  for (int idx = tid; idx < 8*128; idx += 256){
    int bb = idx >> 7, c = idx & 127;
    const float* sp = state + (size_t)(b0+bb)*ADIM*C_ + c;
    float s = 0.f;
    #pragma unroll
    for (int i = 0; i < ADIM; i++) s += sp[i*C_];
    sbar[idx] = s * (1.0f/14.0f);
  }
  __syncthreads();
  #pragma unroll
  for (int u = 0; u < 4; u++){
    int o = tid + u*256;
    int bb = o >> 7, h = o & 127;
    const float* sb = sbar + bb*128;
    const float* w  = cw + h*129;
    float acc = 0.f;
    #pragma unroll 8
    for (int c = 0; c < 128; c++) acc += sb[c]*w[c];
    gg[o] = fmaxf(acc + conv_b[h], 0.f);
  }
  __syncthreads();
  for (int idx = tid; idx < 8*ADIM*C_; idx += 256){
    int bb = idx / (ADIM*C_); int rem = idx - bb*(ADIM*C_);
    int c  = rem & 127;
    size_t node = (size_t)(b0+bb)*ADIM + (rem >> 7);
    g_Xh[node*C_ + c] = __float2half(gg[bb*128 + c] + state[node*C_ + c]);
  }
}

// ---------------- K2: Y = X @ Wcat^T, fp16 out, b1 folded ----------------
__global__ __launch_bounds__(256,1)
void k2_ygemm(const float* __restrict__ lin1_b){
  extern __shared__ __half sm2[];
  __half* As = sm2;             // 128 x 136
  __half* Bs = As + 128*136;    // 128 x 136
  int tid = threadIdx.x;
  int m0 = blockIdx.x * 128, n0 = blockIdx.y * 128;

  for (int idx = tid; idx < 128*16; idx += 256){
    int r = idx >> 4, c = idx & 15;
    *(uint4*)&As[r*136 + c*8] = *(const uint4*)&g_Xh [(size_t)(m0+r)*C_ + c*8];
    *(uint4*)&Bs[r*136 + c*8] = *(const uint4*)&g_Wcat[(size_t)(n0+r)*C_ + c*8];
  }
  __syncthreads();

  int lane = tid & 31, warp = tid >> 5, wm = warp >> 2, wn = warp & 3;
  unsigned abase = (unsigned)__cvta_generic_to_shared(As);
  unsigned bbase = (unsigned)__cvta_generic_to_shared(Bs);
  float acc[4][4][4];
  #pragma unroll
  for (int i=0;i<4;i++) for (int j=0;j<4;j++) for (int q=0;q<4;q++) acc[i][j][q]=0.f;

  int rA = (lane & 7) + ((lane >> 3) & 1) * 8;
  int cA = (lane >> 4) * 8;
  int l16 = lane & 15;
  int rB = l16 & 7;
  int cB = (l16 >> 3) * 8;

  #pragma unroll
  for (int kk = 0; kk < 8; kk++){
    int k0 = kk*16;
    unsigned a[4][4], b[4][2];
    #pragma unroll
    for (int mi = 0; mi < 4; mi++){
      int row = wm*64 + mi*16 + rA;
      ldsm_x4(a[mi][0],a[mi][1],a[mi][2],a[mi][3], abase + (row*136 + k0 + cA)*2);
    }
    #pragma unroll
    for (int ni = 0; ni < 4; ni++){
      int row = wn*32 + ni*8 + rB;
      ldsm_x2(b[ni][0],b[ni][1], bbase + (row*136 + k0 + cB)*2);
    }
    #pragma unroll
    for (int mi = 0; mi < 4; mi++)
      #pragma unroll
      for (int ni = 0; ni < 4; ni++)
        mma16816(acc[mi][ni], a[mi], b[ni]);
  }
  bool leftblk = (n0 < 256);
  #pragma unroll
  for (int ni = 0; ni < 4; ni++){
    int col = n0 + wn*32 + ni*8 + ((lane & 3) << 1);
    float a0 = leftblk ? __ldg(&lin1_b[col])   : 0.f;
    float a1 = leftblk ? __ldg(&lin1_b[col+1]) : 0.f;
    #pragma unroll
    for (int mi = 0; mi < 4; mi++){
      int row = m0 + wm*64 + mi*16 + (lane >> 2);
      *(__half2*)&g_Yh[(size_t)row*512 + col] =
        __floats2half2_rn(acc[mi][ni][0] + a0, acc[mi][ni][1] + a1);
      *(__half2*)&g_Yh[(size_t)(row+8)*512 + col] =
        __floats2half2_rn(acc[mi][ni][2] + a0, acc[mi][ni][3] + a1);
    }
  }
}

// ---------------- K3: 16 GEMM warps (m32 x n32, 2m x 8n) + 4 builders ----------------
// 640 threads: warps 0-15 = GEMM (chunk M=64, 6 chunks/pair), warps 16-19 = builders.
// Barriers: ready=1,2 (builders arrive 128, GEMM sync 512 -> count 640);
//           free=3,4  (GEMM arrive 512, builders sync 128 -> count 640);
//           Ys-guard=5 (builders only, count 128).
__global__ __launch_bounds__(640,1)
void k3_main(const float* __restrict__ lin2_b,
             const float* __restrict__ mu_w, const float* __restrict__ sig_w){
  extern __shared__ __half sm3[];
  __half* Ys  = sm3;                 // 2 x 14 x 512 = 14336 halves (one pair)
  __half* W2s = Ys + 14336;          // 256 x 264 = 67584
  __half* H1a = W2s + 67584;         // 64 x 264
  __half* H1b = H1a + 16896;         // 64 x 264
  // total (14336 + 67584 + 2*16896)*2 = 231424 B

  int tid  = threadIdx.x;
  int lane = tid & 31, warp = tid >> 5;          // 20 warps
  bool isg = (warp < 16);
  int warp_m = (warp >> 3) & 1;                  // 0..1 (GEMM)
  int warp_n = warp & 7;                         // 0..7 (GEMM)
  int bt = tid & 127;                            // builder-local index

  // one-time: W2 into smem (stride 264)
  for (int idx = tid; idx < 256*32; idx += 640){
    int r = idx >> 5, c = idx & 31;
    *(uint4*)&W2s[r*264 + c*8] = ((const uint4*)g_W2h)[r*32 + c];
  }
  // GEMM-warp constants: b2 slice + head-weight B-fragments (R15-proven mapping)
  __half2 b2c[4];
  unsigned bw[2][2];
  if (isg){
    #pragma unroll
    for (int ni = 0; ni < 4; ni++){
      int col = warp_n*32 + ni*8 + ((lane & 3) << 1);
      b2c[ni] = __floats2half2_rn(__ldg(&lin2_b[col]), __ldg(&lin2_b[col+1]));
    }
    int hn = lane >> 2;
    const float* wsrc = (hn == 0) ? mu_w : sig_w;
    #pragma unroll
    for (int f = 0; f < 2; f++){
      int kb = warp_n*32 + f*16 + ((lane & 3) << 1);
      __half2 lo = (hn < 2) ? __floats2half2_rn(__ldg(&wsrc[kb]),   __ldg(&wsrc[kb+1]))
                            : __float2half2_rn(0.f);
      __half2 hi = (hn < 2) ? __floats2half2_rn(__ldg(&wsrc[kb+8]), __ldg(&wsrc[kb+9]))
                            : __float2half2_rn(0.f);
      bw[f][0] = *(unsigned*)&lo;
      bw[f][1] = *(unsigned*)&hi;
    }
  }

  unsigned h1bs[2] = { (unsigned)__cvta_generic_to_shared(H1a),
                       (unsigned)__cvta_generic_to_shared(H1b) };
  __half* H1p[2] = { H1a, H1b };
  unsigned ysb = (unsigned)__cvta_generic_to_shared(Ys);
  unsigned w2b = (unsigned)__cvta_generic_to_shared(W2s);
  int rA  = (lane & 7) + ((lane >> 3) & 1) * 8;
  int cA  = (lane >> 4) * 8;
  int rB4 = lane & 15;
  int cB4 = (lane >> 4) * 8;

  const __half2 zero2 = __float2half2_rn(0.f);
  const __half2 s01   = __float2half2_rn(0.01f);

  int pstep = gridDim.x;

  // initial Ys prefetch (builders only)
  if (!isg && blockIdx.x < NPAIR){
    const __half* src = g_Yh + (size_t)(blockIdx.x*2)*ADIM*512;
    for (int g = bt; g < 1792; g += 128) cp16(ysb + g*16, src + g*8);
    CP_COMMIT();
  }
  __syncthreads();   // W2s visible to all

  if (isg){
    // ================= GEMM role =================
    for (int pair = blockIdx.x; pair < NPAIR; pair += pstep){
      #pragma unroll 1
      for (int t = 0; t < 6; t++){
        int buf = t & 1;
        BAR_SYNC(1 + buf, 640);              // H1[buf] ready
        unsigned h1b = h1bs[buf];

        float acc[2][4][4];
        #pragma unroll
        for (int i=0;i<2;i++) for (int j=0;j<4;j++) for (int q=0;q<4;q++) acc[i][j][q]=0.f;

        unsigned a[2][2][4], bq[2][2][4];
        #pragma unroll
        for (int mi = 0; mi < 2; mi++){
          int row = warp_m*32 + mi*16 + rA;
          ldsm_x4(a[0][mi][0],a[0][mi][1],a[0][mi][2],a[0][mi][3], h1b + (row*264 + cA)*2);
        }
        #pragma unroll
        for (int nj = 0; nj < 2; nj++){
          int row = warp_n*32 + nj*16 + rB4;
          ldsm_x4(bq[0][nj][0],bq[0][nj][1],bq[0][nj][2],bq[0][nj][3], w2b + (row*264 + cB4)*2);
        }
        #pragma unroll
        for (int kk = 0; kk < 16; kk++){
          int cb = kk & 1, nb = cb ^ 1;
          if (kk < 15){
            int k1 = (kk+1)*16;
            #pragma unroll
            for (int mi = 0; mi < 2; mi++){
              int row = warp_m*32 + mi*16 + rA;
              ldsm_x4(a[nb][mi][0],a[nb][mi][1],a[nb][mi][2],a[nb][mi][3],
                      h1b + (row*264 + k1 + cA)*2);
            }
            #pragma unroll
            for (int nj = 0; nj < 2; nj++){
              int row = warp_n*32 + nj*16 + rB4;
              ldsm_x4(bq[nb][nj][0],bq[nb][nj][1],bq[nb][nj][2],bq[nb][nj][3],
                      w2b + (row*264 + k1 + cB4)*2);
            }
          }
          // bq regs: r0 = n0-7/k0-7, r1 = n8-15/k0-7, r2 = n0-7/k8-15, r3 = n8-15/k8-15
          #pragma unroll
          for (int mi = 0; mi < 2; mi++)
            #pragma unroll
            for (int nj = 0; nj < 2; nj++){
              mma16816s(acc[mi][2*nj],   a[cb][mi], bq[cb][nj][0], bq[cb][nj][2]);
              mma16816s(acc[mi][2*nj+1], a[cb][mi], bq[cb][nj][1], bq[cb][nj][3]);
            }
        }
        BAR_ARRIVE(3 + buf, 640);            // H1[buf] free

        // ---- epilogue via mma: lky(acc+b2) repacked as A-frags, dot [mu;sig] ----
        float2* pbase = g_part + ((size_t)pair*384 + t*64)*8 + warp_n;
        #pragma unroll
        for (int mi = 0; mi < 2; mi++){
          float v[4][4];
          #pragma unroll
          for (int ni = 0; ni < 4; ni++){
            float2 bb = __half22float2(b2c[ni]);
            v[ni][0] = lky(acc[mi][ni][0] + bb.x);
            v[ni][1] = lky(acc[mi][ni][1] + bb.y);
            v[ni][2] = lky(acc[mi][ni][2] + bb.x);
            v[ni][3] = lky(acc[mi][ni][3] + bb.y);
          }
          unsigned af[2][4];
          #pragma unroll
          for (int f = 0; f < 2; f++){
            __half2 h0 = __floats2half2_rn(v[2*f][0],   v[2*f][1]);
            __half2 h1 = __floats2half2_rn(v[2*f][2],   v[2*f][3]);
            __half2 h2 = __floats2half2_rn(v[2*f+1][0], v[2*f+1][1]);
            __half2 h3 = __floats2half2_rn(v[2*f+1][2], v[2*f+1][3]);
            af[f][0] = *(unsigned*)&h0;  af[f][1] = *(unsigned*)&h1;
            af[f][2] = *(unsigned*)&h2;  af[f][3] = *(unsigned*)&h3;
          }
          float dc[4] = {0.f, 0.f, 0.f, 0.f};
          mma16816s(dc, af[0], bw[0][0], bw[0][1]);
          mma16816s(dc, af[1], bw[1][0], bw[1][1]);
          if ((lane & 3) == 0){
            int row = warp_m*32 + mi*16 + (lane >> 2);
            pbase[(size_t)row*8]     = make_float2(dc[0], dc[1]);
            pbase[(size_t)(row+8)*8] = make_float2(dc[2], dc[3]);
          }
        }
      }
    }
  } else {
    // ================= builder role =================
    int gc = 0;
    for (int pair = blockIdx.x; pair < NPAIR; pair += pstep){
      CP_WAIT0();                          // own cp.async groups done
      BAR_SYNC(5, 128);                    // ALL builders' Ys writes visible
      #pragma unroll 1
      for (int t = 0; t < 6; t++){
        int buf = t & 1;
        if (gc >= 2) BAR_SYNC(3 + buf, 640);   // wait GEMM done with H1[buf]
        __half* H1d = H1p[buf];
        #pragma unroll
        for (int it = 0; it < 16; it++){
          int idx = bt + it*128;           // 64*32 entries
          int m  = idx >> 5;
          int c8 = idx & 31;
          int rg = t*64 + m;               // 0..383
          int bsel = (rg >= 192) ? 1 : 0;
          int e = rg - 192*bsel;
          uint4 val;
          if (e < E_){
            int ii = e/13; int r = e - ii*13; int jj = r + (r >= ii ? 1 : 0);
            uint4 ul = *(const uint4*)&Ys[(bsel*ADIM + ii)*512 + c8*8];
            uint4 ur = *(const uint4*)&Ys[(bsel*ADIM + jj)*512 + 256 + c8*8];
            const __half2* l2 = (const __half2*)&ul;
            const __half2* r2 = (const __half2*)&ur;
            __half2 o[4];
            #pragma unroll
            for (int q = 0; q < 4; q++){
              __half2 s = __hadd2(l2[q], r2[q]);
              o[q] = __hadd2(__hmax2(s, zero2), __hmul2(s01, __hmin2(s, zero2)));
            }
            val = *(uint4*)o;
          } else {
            val = make_uint4(0u,0u,0u,0u);
          }
          *(uint4*)&H1d[m*264 + c8*8] = val;
        }
        BAR_ARRIVE(1 + buf, 640);          // H1[buf] ready
        gc++;
      }
      BAR_SYNC(5, 128);                    // all builders done READING Ys
      // Ys dead: prefetch next pair
      int pn = pair + pstep;
      if (pn < NPAIR){
        const __half* src = g_Yh + (size_t)(pn*2)*ADIM*512;
        for (int g = bt; g < 1792; g += 128) cp16(ysb + g*16, src + g*8);
      }
      CP_COMMIT();
    }
  }
}

// ---------------- K4: heads + log-prob from partials ----------------
__global__ __launch_bounds__(192,1)
void k4_heads(const float* __restrict__ mu_b, const float* __restrict__ sig_b,
              const float* __restrict__ noise, float* __restrict__ out){
  __shared__ float wsum[6];
  int b = blockIdx.x;                 // 0..2047
  int tid = threadIdx.x;              // 0..191
  int pair = b >> 1, half = b & 1;
  const float2* src = g_part + ((size_t)pair*384 + half*192 + tid)*8;
  float mp = mu_b[0], sp = sig_b[0];
  #pragma unroll
  for (int q = 0; q < 8; q++){ float2 v = src[q]; mp += v.x; sp += v.y; }
  float c = 0.f;
  if (tid < E_){
    float mu = softplus_(mp);
    float sd = softplus_(sp);
    float nz = noise[(size_t)b*E_ + tid];
    out[(size_t)b*E_ + tid] = mu + sd*nz;
    c = -0.5f*nz*nz - logf(sd);
  }
  c += __shfl_xor_sync(0xffffffffu, c, 1);
  c += __shfl_xor_sync(0xffffffffu, c, 2);
  c += __shfl_xor_sync(0xffffffffu, c, 4);
  c += __shfl_xor_sync(0xffffffffu, c, 8);
  c += __shfl_xor_sync(0xffffffffu, c, 16);
  if ((tid & 31) == 0) wsum[tid >> 5] = c;
  __syncthreads();
  if (tid == 0){
    float s = wsum[0] + wsum[1] + wsum[2] + wsum[3] + wsum[4] + wsum[5];
    out[(size_t)NROWS + b] = s - (float)E_ * 0.91893853320467274f;
  }
}

// ---------------- host launcher ----------------
extern "C" void kernel_launch(void* const* d_in, const int* in_sizes, int n_in,
                              void* d_out, int out_size){
  const float* state  = (const float*)d_in[0];
  const float* conv_w = (const float*)d_in[1];
  const float* conv_b = (const float*)d_in[2];
  const float* lin1_w = (const float*)d_in[3];
  const float* lin1_b = (const float*)d_in[4];
  const float* lin2_w = (const float*)d_in[5];
  const float* lin2_b = (const float*)d_in[6];
  const float* mu_w   = (const float*)d_in[7];
  const float* mu_b   = (const float*)d_in[8];
  const float* sig_w  = (const float*)d_in[9];
  const float* sig_b  = (const float*)d_in[10];
  const float* noise  = (const float*)d_in[11];
  float* out = (float*)d_out;

  const int SM1 = (128*129 + 8*128 + 8*128) * 4;           // 74240
  const int SM2 = 2 * 128*136 * 2;                         // 69632
  const int SM3 = (14336 + 256*264 + 2*64*264) * 2;        // 231424

  cudaFuncSetAttribute(k1_build, cudaFuncAttributeMaxDynamicSharedMemorySize, SM1);
  cudaFuncSetAttribute(k2_ygemm, cudaFuncAttributeMaxDynamicSharedMemorySize, SM2);
  cudaFuncSetAttribute(k3_main,  cudaFuncAttributeMaxDynamicSharedMemorySize, SM3);

  k1_build<<<256, 256, SM1>>>(state, conv_w, conv_b, lin1_w, lin2_w);
  k2_ygemm<<<dim3(224, 4), 256, SM2>>>(lin1_b);
  k3_main<<<152, 640, SM3>>>(lin2_b, mu_w, sig_w);
  k4_heads<<<B_, 192>>>(mu_b, sig_b, noise, out);
}

// round 17
// speedup vs baseline: 1.3540x; 1.0262x over previous
#include <cuda_runtime.h>
#include <cuda_fp16.h>
#include <cstdint>

#define B_      2048
#define ADIM    14
#define C_      128
#define H_      256
#define E_      182
#define NNODES  (B_*ADIM)   /* 28672 */
#define NROWS   (B_*E_)     /* 372736 */
#define NPAIR   (B_/2)      /* 1024 */

// ---------------- device scratch (no allocs allowed) ----------------
__device__ __align__(16) __half g_W2h [H_*H_];        // lin2_w fp16
__device__ __align__(16) __half g_Wcat[512*C_];       // [W_left | W_right] rows, k-contig
__device__ __align__(16) __half g_CWh [C_*C_];        // conv_w fp16
__device__ __align__(16) __half g_Sbh [B_*C_];        // sbar fp16 (2048 x 128)
__device__ __align__(16) float  g_G   [B_*C_];        // relu(conv) fp32 (2048 x 128)
__device__ __align__(16) __half g_Xh  [NNODES*C_];    // x = g + state, fp16
__device__ __align__(16) __half g_Yh  [(size_t)NNODES*512]; // [yl(256,+b1) | yr(256)] fp16
__device__ __align__(16) float2 g_part[(size_t)NPAIR*384*8]; // (pm,ps) per (pair,row,ngroup)

// ---------------- mma / barrier helpers ----------------
__device__ __forceinline__ void ldsm_x4(unsigned &r0,unsigned &r1,unsigned &r2,unsigned &r3, unsigned a){
  asm volatile("ldmatrix.sync.aligned.m8n8.x4.shared.b16 {%0,%1,%2,%3},[%4];"
    :"=r"(r0),"=r"(r1),"=r"(r2),"=r"(r3):"r"(a));
}
__device__ __forceinline__ void ldsm_x2(unsigned &r0,unsigned &r1, unsigned a){
  asm volatile("ldmatrix.sync.aligned.m8n8.x2.shared.b16 {%0,%1},[%2];"
    :"=r"(r0),"=r"(r1):"r"(a));
}
__device__ __forceinline__ void mma16816(float c[4], const unsigned a[4], const unsigned b[2]){
  asm volatile("mma.sync.aligned.m16n8k16.row.col.f32.f16.f16.f32 "
    "{%0,%1,%2,%3},{%4,%5,%6,%7},{%8,%9},{%0,%1,%2,%3};"
    :"+f"(c[0]),"+f"(c[1]),"+f"(c[2]),"+f"(c[3])
    :"r"(a[0]),"r"(a[1]),"r"(a[2]),"r"(a[3]),"r"(b[0]),"r"(b[1]));
}
__device__ __forceinline__ void mma16816s(float c[4], const unsigned a[4], unsigned b0, unsigned b1){
  asm volatile("mma.sync.aligned.m16n8k16.row.col.f32.f16.f16.f32 "
    "{%0,%1,%2,%3},{%4,%5,%6,%7},{%8,%9},{%0,%1,%2,%3};"
    :"+f"(c[0]),"+f"(c[1]),"+f"(c[2]),"+f"(c[3])
    :"r"(a[0]),"r"(a[1]),"r"(a[2]),"r"(a[3]),"r"(b0),"r"(b1));
}
__device__ __forceinline__ void cp16(unsigned dst, const void* src){
  asm volatile("cp.async.cg.shared.global [%0], [%1], 16;" :: "r"(dst), "l"(src));
}
#define CP_COMMIT() asm volatile("cp.async.commit_group;" ::: "memory")
#define CP_WAIT0()  asm volatile("cp.async.wait_group 0;" ::: "memory")
#define BAR_SYNC(id, n)   asm volatile("bar.sync %0, %1;"   :: "r"(id), "r"(n) : "memory")
#define BAR_ARRIVE(id, n) asm volatile("bar.arrive %0, %1;" :: "r"(id), "r"(n) : "memory")

__device__ __forceinline__ float lky(float v){ return v > 0.f ? v : 0.01f*v; }
__device__ __forceinline__ float softplus_(float x){ return fmaxf(x,0.f) + log1pf(expf(-fabsf(x))); }

// ---------------- K1a: weight converts + sbar ----------------
__global__ __launch_bounds__(256,2)
void k1a_prep(const float* __restrict__ state,
              const float* __restrict__ conv_w,
              const float* __restrict__ lin1_w, const float* __restrict__ lin2_w){
  int i = blockIdx.x*256 + threadIdx.x;      // 0 .. 262143
  if (i < H_*H_) g_W2h[i] = __float2half(lin2_w[i]);
  if (i < 512*C_){
    int o = i >> 7, c = i & 127;
    float v = (o < H_) ? lin1_w[o*(2*C_) + c] : lin1_w[(o-H_)*(2*C_) + C_ + c];
    g_Wcat[i] = __float2half(v);
  }
  if (i < C_*C_) g_CWh[i] = __float2half(conv_w[i]);
  // sbar: i -> (b, c)
  int b = i >> 7, c = i & 127;
  const float* sp = state + (size_t)b*ADIM*C_ + c;
  float s = 0.f;
  #pragma unroll
  for (int j = 0; j < ADIM; j++) s += sp[j*C_];
  g_Sbh[i] = __float2half(s * (1.0f/14.0f));
}

// ---------------- K1b: G = relu(sbar @ CW^T + cb), k2-pattern GEMM ----------------
__global__ __launch_bounds__(256,1)
void k1b_conv(const float* __restrict__ conv_b){
  extern __shared__ __half sm1[];
  __half* As = sm1;             // 128 x 136
  __half* Bs = As + 128*136;    // 128 x 136
  int tid = threadIdx.x;
  int m0 = blockIdx.x * 128;

  for (int idx = tid; idx < 128*16; idx += 256){
    int r = idx >> 4, c = idx & 15;
    *(uint4*)&As[r*136 + c*8] = *(const uint4*)&g_Sbh[(size_t)(m0+r)*C_ + c*8];
    *(uint4*)&Bs[r*136 + c*8] = *(const uint4*)&g_CWh[(size_t)r*C_ + c*8];
  }
  __syncthreads();

  int lane = tid & 31, warp = tid >> 5, wm = warp >> 2, wn = warp & 3;
  unsigned abase = (unsigned)__cvta_generic_to_shared(As);
  unsigned bbase = (unsigned)__cvta_generic_to_shared(Bs);
  float acc[4][4][4];
  #pragma unroll
  for (int i=0;i<4;i++) for (int j=0;j<4;j++) for (int q=0;q<4;q++) acc[i][j][q]=0.f;

  int rA = (lane & 7) + ((lane >> 3) & 1) * 8;
  int cA = (lane >> 4) * 8;
  int l16 = lane & 15;
  int rB = l16 & 7;
  int cB = (l16 >> 3) * 8;

  #pragma unroll
  for (int kk = 0; kk < 8; kk++){
    int k0 = kk*16;
    unsigned a[4][4], b[4][2];
    #pragma unroll
    for (int mi = 0; mi < 4; mi++){
      int row = wm*64 + mi*16 + rA;
      ldsm_x4(a[mi][0],a[mi][1],a[mi][2],a[mi][3], abase + (row*136 + k0 + cA)*2);
    }
    #pragma unroll
    for (int ni = 0; ni < 4; ni++){
      int row = wn*32 + ni*8 + rB;
      ldsm_x2(b[ni][0],b[ni][1], bbase + (row*136 + k0 + cB)*2);
    }
    #pragma unroll
    for (int mi = 0; mi < 4; mi++)
      #pragma unroll
      for (int ni = 0; ni < 4; ni++)
        mma16816(acc[mi][ni], a[mi], b[ni]);
  }
  #pragma unroll
  for (int ni = 0; ni < 4; ni++){
    int col = wn*32 + ni*8 + ((lane & 3) << 1);
    float c0 = __ldg(&conv_b[col]);
    float c1 = __ldg(&conv_b[col+1]);
    #pragma unroll
    for (int mi = 0; mi < 4; mi++){
      int row = m0 + wm*64 + mi*16 + (lane >> 2);
      *(float2*)&g_G[(size_t)row*C_ + col] =
        make_float2(fmaxf(acc[mi][ni][0] + c0, 0.f), fmaxf(acc[mi][ni][1] + c1, 0.f));
      *(float2*)&g_G[(size_t)(row+8)*C_ + col] =
        make_float2(fmaxf(acc[mi][ni][2] + c0, 0.f), fmaxf(acc[mi][ni][3] + c1, 0.f));
    }
  }
}

// ---------------- K1c: X = half(state + G[batch]) ----------------
__global__ __launch_bounds__(256,2)
void k1c_x(const float* __restrict__ state){
  int nb = blockIdx.x * 128;                 // node base
  int tid = threadIdx.x;
  #pragma unroll
  for (int it = 0; it < 8; it++){
    int idx = tid + it*256;                  // 128 rows x 16 groups of 8 cols
    int r  = idx >> 4;
    int c8 = (idx & 15) << 3;                // col*8
    int node = nb + r;
    int batch = node / ADIM;
    const float4* sp = (const float4*)&state[(size_t)node*C_ + c8];
    const float4* gp = (const float4*)&g_G[(size_t)batch*C_ + c8];
    float4 s0 = sp[0], s1 = sp[1];
    float4 q0 = gp[0], q1 = gp[1];
    __half2 o[4];
    o[0] = __floats2half2_rn(s0.x + q0.x, s0.y + q0.y);
    o[1] = __floats2half2_rn(s0.z + q0.z, s0.w + q0.w);
    o[2] = __floats2half2_rn(s1.x + q1.x, s1.y + q1.y);
    o[3] = __floats2half2_rn(s1.z + q1.z, s1.w + q1.w);
    *(uint4*)&g_Xh[(size_t)node*C_ + c8] = *(uint4*)o;
  }
}

// ---------------- K2: Y = X @ Wcat^T, fp16 out, b1 folded ----------------
__global__ __launch_bounds__(256,1)
void k2_ygemm(const float* __restrict__ lin1_b){
  extern __shared__ __half sm2[];
  __half* As = sm2;             // 128 x 136
  __half* Bs = As + 128*136;    // 128 x 136
  int tid = threadIdx.x;
  int m0 = blockIdx.x * 128, n0 = blockIdx.y * 128;

  for (int idx = tid; idx < 128*16; idx += 256){
    int r = idx >> 4, c = idx & 15;
    *(uint4*)&As[r*136 + c*8] = *(const uint4*)&g_Xh [(size_t)(m0+r)*C_ + c*8];
    *(uint4*)&Bs[r*136 + c*8] = *(const uint4*)&g_Wcat[(size_t)(n0+r)*C_ + c*8];
  }
  __syncthreads();

  int lane = tid & 31, warp = tid >> 5, wm = warp >> 2, wn = warp & 3;
  unsigned abase = (unsigned)__cvta_generic_to_shared(As);
  unsigned bbase = (unsigned)__cvta_generic_to_shared(Bs);
  float acc[4][4][4];
  #pragma unroll
  for (int i=0;i<4;i++) for (int j=0;j<4;j++) for (int q=0;q<4;q++) acc[i][j][q]=0.f;

  int rA = (lane & 7) + ((lane >> 3) & 1) * 8;
  int cA = (lane >> 4) * 8;
  int l16 = lane & 15;
  int rB = l16 & 7;
  int cB = (l16 >> 3) * 8;

  #pragma unroll
  for (int kk = 0; kk < 8; kk++){
    int k0 = kk*16;
    unsigned a[4][4], b[4][2];
    #pragma unroll
    for (int mi = 0; mi < 4; mi++){
      int row = wm*64 + mi*16 + rA;
      ldsm_x4(a[mi][0],a[mi][1],a[mi][2],a[mi][3], abase + (row*136 + k0 + cA)*2);
    }
    #pragma unroll
    for (int ni = 0; ni < 4; ni++){
      int row = wn*32 + ni*8 + rB;
      ldsm_x2(b[ni][0],b[ni][1], bbase + (row*136 + k0 + cB)*2);
    }
    #pragma unroll
    for (int mi = 0; mi < 4; mi++)
      #pragma unroll
      for (int ni = 0; ni < 4; ni++)
        mma16816(acc[mi][ni], a[mi], b[ni]);
  }
  bool leftblk = (n0 < 256);
  #pragma unroll
  for (int ni = 0; ni < 4; ni++){
    int col = n0 + wn*32 + ni*8 + ((lane & 3) << 1);
    float a0 = leftblk ? __ldg(&lin1_b[col])   : 0.f;
    float a1 = leftblk ? __ldg(&lin1_b[col+1]) : 0.f;
    #pragma unroll
    for (int mi = 0; mi < 4; mi++){
      int row = m0 + wm*64 + mi*16 + (lane >> 2);
      *(__half2*)&g_Yh[(size_t)row*512 + col] =
        __floats2half2_rn(acc[mi][ni][0] + a0, acc[mi][ni][1] + a1);
      *(__half2*)&g_Yh[(size_t)(row+8)*512 + col] =
        __floats2half2_rn(acc[mi][ni][2] + a0, acc[mi][ni][3] + a1);
    }
  }
}

// ---------------- K3: 16 GEMM warps (m32 x n32, 2m x 8n) + 4 builders ----------------
__global__ __launch_bounds__(640,1)
void k3_main(const float* __restrict__ lin2_b,
             const float* __restrict__ mu_w, const float* __restrict__ sig_w){
  extern __shared__ __half sm3[];
  __half* Ys  = sm3;                 // 2 x 14 x 512 = 14336 halves (one pair)
  __half* W2s = Ys + 14336;          // 256 x 264 = 67584
  __half* H1a = W2s + 67584;         // 64 x 264
  __half* H1b = H1a + 16896;         // 64 x 264

  int tid  = threadIdx.x;
  int lane = tid & 31, warp = tid >> 5;          // 20 warps
  bool isg = (warp < 16);
  int warp_m = (warp >> 3) & 1;
  int warp_n = warp & 7;
  int bt = tid & 127;

  for (int idx = tid; idx < 256*32; idx += 640){
    int r = idx >> 5, c = idx & 31;
    *(uint4*)&W2s[r*264 + c*8] = ((const uint4*)g_W2h)[r*32 + c];
  }
  __half2 b2c[4];
  unsigned bw[2][2];
  if (isg){
    #pragma unroll
    for (int ni = 0; ni < 4; ni++){
      int col = warp_n*32 + ni*8 + ((lane & 3) << 1);
      b2c[ni] = __floats2half2_rn(__ldg(&lin2_b[col]), __ldg(&lin2_b[col+1]));
    }
    int hn = lane >> 2;
    const float* wsrc = (hn == 0) ? mu_w : sig_w;
    #pragma unroll
    for (int f = 0; f < 2; f++){
      int kb = warp_n*32 + f*16 + ((lane & 3) << 1);
      __half2 lo = (hn < 2) ? __floats2half2_rn(__ldg(&wsrc[kb]),   __ldg(&wsrc[kb+1]))
                            : __float2half2_rn(0.f);
      __half2 hi = (hn < 2) ? __floats2half2_rn(__ldg(&wsrc[kb+8]), __ldg(&wsrc[kb+9]))
                            : __float2half2_rn(0.f);
      bw[f][0] = *(unsigned*)&lo;
      bw[f][1] = *(unsigned*)&hi;
    }
  }

  unsigned h1bs[2] = { (unsigned)__cvta_generic_to_shared(H1a),
                       (unsigned)__cvta_generic_to_shared(H1b) };
  __half* H1p[2] = { H1a, H1b };
  unsigned ysb = (unsigned)__cvta_generic_to_shared(Ys);
  unsigned w2b = (unsigned)__cvta_generic_to_shared(W2s);
  int rA  = (lane & 7) + ((lane >> 3) & 1) * 8;
  int cA  = (lane >> 4) * 8;
  int rB4 = lane & 15;
  int cB4 = (lane >> 4) * 8;

  const __half2 zero2 = __float2half2_rn(0.f);
  const __half2 s01   = __float2half2_rn(0.01f);

  int pstep = gridDim.x;

  if (!isg && blockIdx.x < NPAIR){
    const __half* src = g_Yh + (size_t)(blockIdx.x*2)*ADIM*512;
    for (int g = bt; g < 1792; g += 128) cp16(ysb + g*16, src + g*8);
    CP_COMMIT();
  }
  __syncthreads();

  if (isg){
    for (int pair = blockIdx.x; pair < NPAIR; pair += pstep){
      #pragma unroll 1
      for (int t = 0; t < 6; t++){
        int buf = t & 1;
        BAR_SYNC(1 + buf, 640);
        unsigned h1b = h1bs[buf];

        float acc[2][4][4];
        #pragma unroll
        for (int i=0;i<2;i++) for (int j=0;j<4;j++) for (int q=0;q<4;q++) acc[i][j][q]=0.f;

        unsigned a[2][2][4], bq[2][2][4];
        #pragma unroll
        for (int mi = 0; mi < 2; mi++){
          int row = warp_m*32 + mi*16 + rA;
          ldsm_x4(a[0][mi][0],a[0][mi][1],a[0][mi][2],a[0][mi][3], h1b + (row*264 + cA)*2);
        }
        #pragma unroll
        for (int nj = 0; nj < 2; nj++){
          int row = warp_n*32 + nj*16 + rB4;
          ldsm_x4(bq[0][nj][0],bq[0][nj][1],bq[0][nj][2],bq[0][nj][3], w2b + (row*264 + cB4)*2);
        }
        #pragma unroll
        for (int kk = 0; kk < 16; kk++){
          int cb = kk & 1, nb = cb ^ 1;
          if (kk < 15){
            int k1 = (kk+1)*16;
            #pragma unroll
            for (int mi = 0; mi < 2; mi++){
              int row = warp_m*32 + mi*16 + rA;
              ldsm_x4(a[nb][mi][0],a[nb][mi][1],a[nb][mi][2],a[nb][mi][3],
                      h1b + (row*264 + k1 + cA)*2);
            }
            #pragma unroll
            for (int nj = 0; nj < 2; nj++){
              int row = warp_n*32 + nj*16 + rB4;
              ldsm_x4(bq[nb][nj][0],bq[nb][nj][1],bq[nb][nj][2],bq[nb][nj][3],
                      w2b + (row*264 + k1 + cB4)*2);
            }
          }
          #pragma unroll
          for (int mi = 0; mi < 2; mi++)
            #pragma unroll
            for (int nj = 0; nj < 2; nj++){
              mma16816s(acc[mi][2*nj],   a[cb][mi], bq[cb][nj][0], bq[cb][nj][2]);
              mma16816s(acc[mi][2*nj+1], a[cb][mi], bq[cb][nj][1], bq[cb][nj][3]);
            }
        }
        BAR_ARRIVE(3 + buf, 640);

        float2* pbase = g_part + ((size_t)pair*384 + t*64)*8 + warp_n;
        #pragma unroll
        for (int mi = 0; mi < 2; mi++){
          float v[4][4];
          #pragma unroll
          for (int ni = 0; ni < 4; ni++){
            float2 bb = __half22float2(b2c[ni]);
            v[ni][0] = lky(acc[mi][ni][0] + bb.x);
            v[ni][1] = lky(acc[mi][ni][1] + bb.y);
            v[ni][2] = lky(acc[mi][ni][2] + bb.x);
            v[ni][3] = lky(acc[mi][ni][3] + bb.y);
          }
          unsigned af[2][4];
          #pragma unroll
          for (int f = 0; f < 2; f++){
            __half2 h0 = __floats2half2_rn(v[2*f][0],   v[2*f][1]);
            __half2 h1 = __floats2half2_rn(v[2*f][2],   v[2*f][3]);
            __half2 h2 = __floats2half2_rn(v[2*f+1][0], v[2*f+1][1]);
            __half2 h3 = __floats2half2_rn(v[2*f+1][2], v[2*f+1][3]);
            af[f][0] = *(unsigned*)&h0;  af[f][1] = *(unsigned*)&h1;
            af[f][2] = *(unsigned*)&h2;  af[f][3] = *(unsigned*)&h3;
          }
          float dc[4] = {0.f, 0.f, 0.f, 0.f};
          mma16816s(dc, af[0], bw[0][0], bw[0][1]);
          mma16816s(dc, af[1], bw[1][0], bw[1][1]);
          if ((lane & 3) == 0){
            int row = warp_m*32 + mi*16 + (lane >> 2);
            pbase[(size_t)row*8]     = make_float2(dc[0], dc[1]);
            pbase[(size_t)(row+8)*8] = make_float2(dc[2], dc[3]);
          }
        }
      }
    }
  } else {
    int gc = 0;
    for (int pair = blockIdx.x; pair < NPAIR; pair += pstep){
      CP_WAIT0();
      BAR_SYNC(5, 128);
      #pragma unroll 1
      for (int t = 0; t < 6; t++){
        int buf = t & 1;
        if (gc >= 2) BAR_SYNC(3 + buf, 640);
        __half* H1d = H1p[buf];
        #pragma unroll
        for (int it = 0; it < 16; it++){
          int idx = bt + it*128;
          int m  = idx >> 5;
          int c8 = idx & 31;
          int rg = t*64 + m;
          int bsel = (rg >= 192) ? 1 : 0;
          int e = rg - 192*bsel;
          uint4 val;
          if (e < E_){
            int ii = e/13; int r = e - ii*13; int jj = r + (r >= ii ? 1 : 0);
            uint4 ul = *(const uint4*)&Ys[(bsel*ADIM + ii)*512 + c8*8];
            uint4 ur = *(const uint4*)&Ys[(bsel*ADIM + jj)*512 + 256 + c8*8];
            const __half2* l2 = (const __half2*)&ul;
            const __half2* r2 = (const __half2*)&ur;
            __half2 o[4];
            #pragma unroll
            for (int q = 0; q < 4; q++){
              __half2 s = __hadd2(l2[q], r2[q]);
              o[q] = __hadd2(__hmax2(s, zero2), __hmul2(s01, __hmin2(s, zero2)));
            }
            val = *(uint4*)o;
          } else {
            val = make_uint4(0u,0u,0u,0u);
          }
          *(uint4*)&H1d[m*264 + c8*8] = val;
        }
        BAR_ARRIVE(1 + buf, 640);
        gc++;
      }
      BAR_SYNC(5, 128);
      int pn = pair + pstep;
      if (pn < NPAIR){
        const __half* src = g_Yh + (size_t)(pn*2)*ADIM*512;
        for (int g = bt; g < 1792; g += 128) cp16(ysb + g*16, src + g*8);
      }
      CP_COMMIT();
    }
  }
}

// ---------------- K4: heads + log-prob from partials ----------------
__global__ __launch_bounds__(192,1)
void k4_heads(const float* __restrict__ mu_b, const float* __restrict__ sig_b,
              const float* __restrict__ noise, float* __restrict__ out){
  __shared__ float wsum[6];
  int b = blockIdx.x;
  int tid = threadIdx.x;
  int pair = b >> 1, half = b & 1;
  const float2* src = g_part + ((size_t)pair*384 + half*192 + tid)*8;
  float mp = mu_b[0], sp = sig_b[0];
  #pragma unroll
  for (int q = 0; q < 8; q++){ float2 v = src[q]; mp += v.x; sp += v.y; }
  float c = 0.f;
  if (tid < E_){
    float mu = softplus_(mp);
    float sd = softplus_(sp);
    float nz = noise[(size_t)b*E_ + tid];
    out[(size_t)b*E_ + tid] = mu + sd*nz;
    c = -0.5f*nz*nz - logf(sd);
  }
  c += __shfl_xor_sync(0xffffffffu, c, 1);
  c += __shfl_xor_sync(0xffffffffu, c, 2);
  c += __shfl_xor_sync(0xffffffffu, c, 4);
  c += __shfl_xor_sync(0xffffffffu, c, 8);
  c += __shfl_xor_sync(0xffffffffu, c, 16);
  if ((tid & 31) == 0) wsum[tid >> 5] = c;
  __syncthreads();
  if (tid == 0){
    float s = wsum[0] + wsum[1] + wsum[2] + wsum[3] + wsum[4] + wsum[5];
    out[(size_t)NROWS + b] = s - (float)E_ * 0.91893853320467274f;
  }
}

// ---------------- host launcher ----------------
extern "C" void kernel_launch(void* const* d_in, const int* in_sizes, int n_in,
                              void* d_out, int out_size){
  const float* state  = (const float*)d_in[0];
  const float* conv_w = (const float*)d_in[1];
  const float* conv_b = (const float*)d_in[2];
  const float* lin1_w = (const float*)d_in[3];
  const float* lin1_b = (const float*)d_in[4];
  const float* lin2_w = (const float*)d_in[5];
  const float* lin2_b = (const float*)d_in[6];
  const float* mu_w   = (const float*)d_in[7];
  const float* mu_b   = (const float*)d_in[8];
  const float* sig_w  = (const float*)d_in[9];
  const float* sig_b  = (const float*)d_in[10];
  const float* noise  = (const float*)d_in[11];
  float* out = (float*)d_out;

  const int SM12 = 2 * 128*136 * 2;                        // 69632 (k1b & k2)
  const int SM3  = (14336 + 256*264 + 2*64*264) * 2;       // 231424

  cudaFuncSetAttribute(k1b_conv, cudaFuncAttributeMaxDynamicSharedMemorySize, SM12);
  cudaFuncSetAttribute(k2_ygemm, cudaFuncAttributeMaxDynamicSharedMemorySize, SM12);
  cudaFuncSetAttribute(k3_main,  cudaFuncAttributeMaxDynamicSharedMemorySize, SM3);

  k1a_prep<<<1024, 256>>>(state, conv_w, lin1_w, lin2_w);
  k1b_conv<<<16, 256, SM12>>>(conv_b);
  k1c_x<<<224, 256>>>(state);
  k2_ygemm<<<dim3(224, 4), 256, SM12>>>(lin1_b);
  k3_main<<<152, 640, SM3>>>(lin2_b, mu_w, sig_w);
  k4_heads<<<B_, 192>>>(mu_b, sig_b, noise, out);
}